// round 11
// baseline (speedup 1.0000x reference)
#include <cuda_runtime.h>
#include <cuda_bf16.h>
#include <math.h>
#include <stdint.h>

// Problem constants
#define BB 16
#define TT 2000
#define CC 1536
#define NH 8
#define DD 192
#define QQ 256
#define AA 192

// ===================== warp-MMA helpers (sm_80+ baseline) ==================
__device__ __forceinline__ uint32_t smem_u32(const void* p) {
    uint32_t a;
    asm("{ .reg .u64 t; cvta.to.shared.u64 t, %1; cvt.u32.u64 %0, t; }"
        : "=r"(a) : "l"(p));
    return a;
}
__device__ __forceinline__ void ldsm_x4(uint32_t r[4], uint32_t addr) {
    asm volatile("ldmatrix.sync.aligned.m8n8.x4.shared.b16 {%0,%1,%2,%3}, [%4];"
                 : "=r"(r[0]), "=r"(r[1]), "=r"(r[2]), "=r"(r[3]) : "r"(addr));
}
__device__ __forceinline__ void mma_bf16(float c[4], const uint32_t a[4],
                                         uint32_t b0, uint32_t b1) {
    asm volatile("mma.sync.aligned.m16n8k16.row.col.f32.bf16.bf16.f32 "
                 "{%0,%1,%2,%3}, {%4,%5,%6,%7}, {%8,%9}, {%0,%1,%2,%3};"
                 : "+f"(c[0]), "+f"(c[1]), "+f"(c[2]), "+f"(c[3])
                 : "r"(a[0]), "r"(a[1]), "r"(a[2]), "r"(a[3]), "r"(b0), "r"(b1));
}
__device__ __forceinline__ uint32_t pack_bf(float lo, float hi) {
    uint32_t r;
    asm("cvt.rn.bf16x2.f32 %0, %1, %2;" : "=r"(r) : "f"(hi), "f"(lo));
    return r;
}
__device__ __forceinline__ float bflo(uint32_t u) { return __uint_as_float(u << 16); }
__device__ __forceinline__ float bfhi(uint32_t u) { return __uint_as_float(u & 0xffff0000u); }
__device__ __forceinline__ float tanha(float x) {
    float r; asm("tanh.approx.f32 %0, %1;" : "=f"(r) : "f"(x)); return r;
}
#define CP_ASYNC16(dst, src) \
    asm volatile("cp.async.cg.shared.global [%0], [%1], 16;" :: "r"(dst), "l"(src))
#define CP_COMMIT() asm volatile("cp.async.commit_group;" ::: "memory")
#define CP_WAIT0() asm volatile("cp.async.wait_group 0;" ::: "memory")
#define CP_WAIT1() asm volatile("cp.async.wait_group 1;" ::: "memory")

// ---------------- scratch (device globals: no allocations allowed) --------
__device__ float g_c[BB * CC * 2];
__device__ float g_hck[BB * NH * QQ];
__device__ float g_t1[BB * NH * QQ];
__device__ float g_cq2[BB * NH * AA];
__device__ float g_vcqsum[NH * AA];
__device__ float g_ckdot[BB * NH];
__device__ float g_qdotp[NH * 8];
__device__ float g_qT[NH * AA * QQ];                          // query^T [n][a][q]
__device__ __nv_bfloat16 g_w1t[NH * QQ * DD];                 // W1^T [n][q][d] bf16
__device__ __nv_bfloat16 g_hcqT[(size_t)BB * NH * AA * QQ];   // hcq^T/sqrt(Q) [bn][a][q]
__device__ uint32_t g_hk[(size_t)BB * NH * 32 * 64 * 128];    // raw hk bf16x2 [bn][tile][t][q/2]
__device__ float g_lamt[BB * NH * 32 * 64];                   // lambda_k per (bn, tile, t)
__device__ float4 g_pp[BB * NH * 32 * AA];                    // pool partials per tile

// ---------------- K1: mean/std over time ----------------------------------
__global__ void k_stats(const float* __restrict__ ht) {
    int b = blockIdx.y;
    int ch = blockIdx.x * 128 + threadIdx.x;
    int ty = threadIdx.y;
    float s = 0.f, s2 = 0.f;
    const float* p = ht + (size_t)b * TT * CC + ch;
    for (int t = ty; t < TT; t += 8) {
        float v = p[(size_t)t * CC];
        s += v; s2 += v * v;
    }
    __shared__ float sh0[8][128];
    __shared__ float sh1[8][128];
    sh0[ty][threadIdx.x] = s;
    sh1[ty][threadIdx.x] = s2;
    __syncthreads();
    if (ty == 0) {
        for (int j = 1; j < 8; j++) { s += sh0[j][threadIdx.x]; s2 += sh1[j][threadIdx.x]; }
        float mean = s * (1.f / TT);
        float var = (s2 - (float)TT * mean * mean) * (1.f / (TT - 1));
        float sd = sqrtf(fmaxf(var, 0.f));
        g_c[((size_t)b * CC + ch) * 2 + 0] = mean;
        g_c[((size_t)b * CC + ch) * 2 + 1] = sd;
    }
}

// ---------------- K0: qdot partials + vcq_sum ------------------------------
__global__ void k_qdot(const float* __restrict__ query, const float* __restrict__ vhq,
                       const float* __restrict__ vcq) {
    int s = blockIdx.x;
    int n = blockIdx.y;
    int tid = threadIdx.x;
    float acc = 0.f;
    int base = s * (AA * QQ / 8);
    for (int ii = tid; ii < AA * QQ / 8; ii += 256) {
        int i = base + ii;
        int a = i >> 8, q = i & 255;
        acc += query[(n * QQ + q) * AA + a] * vhq[n * AA * QQ + i];
    }
    __shared__ float red[256];
    red[tid] = acc;
    __syncthreads();
    for (int off = 128; off > 0; off >>= 1) {
        if (tid < off) red[tid] += red[tid + off];
        __syncthreads();
    }
    if (tid == 0) g_qdotp[n * 8 + s] = red[0];

    int w = tid >> 5, lane = tid & 31;
    for (int r = w; r < AA / 8; r += 8) {
        int a = s * (AA / 8) + r;
        const float* vp = vcq + ((size_t)n * AA + a) * QQ;
        float sum = 0.f;
        for (int q = lane; q < QQ; q += 32) sum += vp[q];
#pragma unroll
        for (int o = 16; o > 0; o >>= 1) sum += __shfl_down_sync(0xffffffffu, sum, o);
        if (lane == 0) g_vcqsum[n * AA + a] = sum;
    }
}

// ---------------- prep: W1^T -> bf16 (tiled transpose) ---------------------
__global__ void k_prepw(const float* __restrict__ W1) {
    int n = blockIdx.y;
    int tile = blockIdx.x;
    int d0 = (tile % 6) * 32, q0 = (tile / 6) * 32;
    int tx = threadIdx.x, ty = threadIdx.y;
    __shared__ float tl[32][33];
#pragma unroll
    for (int j = 0; j < 4; j++)
        tl[ty + j * 8][tx] = W1[((size_t)n * DD + d0 + ty + j * 8) * QQ + q0 + tx];
    __syncthreads();
#pragma unroll
    for (int j = 0; j < 4; j++)
        g_w1t[((size_t)n * QQ + q0 + ty + j * 8) * DD + d0 + tx] =
            __float2bfloat16_rn(tl[tx][ty + j * 8]);
}

// ---------------- prep: query^T fp32 (tiled transpose) ---------------------
__global__ void k_prepq(const float* __restrict__ query) {
    int n = blockIdx.y;
    int tile = blockIdx.x;
    int a0 = (tile % 6) * 32, q0 = (tile / 6) * 32;
    int tx = threadIdx.x, ty = threadIdx.y;
    __shared__ float tl[32][33];
#pragma unroll
    for (int j = 0; j < 4; j++)
        tl[ty + j * 8][tx] = query[((size_t)n * QQ + q0 + ty + j * 8) * AA + a0 + tx];
    __syncthreads();
#pragma unroll
    for (int j = 0; j < 4; j++)
        g_qT[((size_t)n * AA + a0 + ty + j * 8) * QQ + q0 + tx] = tl[tx][ty + j * 8];
}

// ---------------- ctx-a: hck + t1 for all 16 b per block -------------------
__global__ __launch_bounds__(256) void k_ctx_a(
        const float* __restrict__ uk_W, const float* __restrict__ u_q1W,
        const float* __restrict__ u_q1b,
        const float* __restrict__ bnc_g, const float* __restrict__ bnc_b,
        const float* __restrict__ bnc_m, const float* __restrict__ bnc_v) {
    int n = blockIdx.y, qt = blockIdx.x;
    int tid = threadIdx.x;
    int qi = tid & 31, sl = tid >> 5;
    int q = qt * 32 + qi;

    __shared__ float c_sh[16 * 384];
    __shared__ float part[8 * 16 * 33];

    for (int i = tid; i < 16 * 384; i += 256) {
        int b = i / 384, l = i - b * 384;
        c_sh[i] = g_c[((size_t)b * CC + n * DD) * 2 + l];
    }
    __syncthreads();

    float ak[16], aq[16];
#pragma unroll
    for (int b = 0; b < 16; b++) { ak[b] = 0.f; aq[b] = 0.f; }
    {
        const float* uk = uk_W + ((size_t)n * 384) * QQ + q;
        const float* u1 = u_q1W + ((size_t)n * 384) * QQ + q;
        int l0 = sl * 48;
        for (int l = l0; l < l0 + 48; l++) {
            float wk = uk[(size_t)l * QQ];
            float w1 = u1[(size_t)l * QQ];
            const float* cb = c_sh + l;
#pragma unroll
            for (int b = 0; b < 16; b++) {
                float cv = cb[b * 384];
                ak[b] = fmaf(cv, wk, ak[b]);
                aq[b] = fmaf(cv, w1, aq[b]);
            }
        }
    }

#pragma unroll
    for (int b = 0; b < 16; b++) part[(sl * 16 + b) * 33 + qi] = ak[b];
    __syncthreads();
    {
        int bp = tid >> 5;
        float s0 = 0.f, s1 = 0.f;
#pragma unroll
        for (int s = 0; s < 8; s++) {
            s0 += part[(s * 16 + bp) * 33 + qi];
            s1 += part[(s * 16 + bp + 8) * 33 + qi];
        }
        g_hck[((size_t)(bp * NH + n)) * QQ + q] = s0;
        g_hck[((size_t)((bp + 8) * NH + n)) * QQ + q] = s1;
    }
    __syncthreads();

#pragma unroll
    for (int b = 0; b < 16; b++) part[(sl * 16 + b) * 33 + qi] = aq[b];
    __syncthreads();
    {
        int bp = tid >> 5;
        float s0 = 0.f, s1 = 0.f;
#pragma unroll
        for (int s = 0; s < 8; s++) {
            s0 += part[(s * 16 + bp) * 33 + qi];
            s1 += part[(s * 16 + bp + 8) * 33 + qi];
        }
        float bias = u_q1b[n * QQ + q];
        float grs = bnc_g[q] * rsqrtf(bnc_v[q] + 1e-5f);
        float beta = bnc_b[q] - grs * bnc_m[q];
        float r0 = fmaxf(s0 + bias, 0.f);
        float r1 = fmaxf(s1 + bias, 0.f);
        g_t1[((size_t)(bp * NH + n)) * QQ + q] = tanhf(fmaf(grs, r0, beta));
        g_t1[((size_t)((bp + 8) * NH + n)) * QQ + q] = tanhf(fmaf(grs, r1, beta));
    }
}

// ---------------- ctx-b: cq2 = t1 @ u_q2 for all 16 b per block ------------
__global__ __launch_bounds__(256) void k_ctx_b(const float* __restrict__ u_q2) {
    int n = blockIdx.y, at = blockIdx.x;
    int tid = threadIdx.x;
    int ai = tid & 31, msl = tid >> 5;
    int a = at * 32 + ai;

    __shared__ float t1_sh[16 * 256];
    __shared__ float part[8 * 16 * 33];

    for (int i = tid; i < 16 * 256; i += 256) {
        int b = i >> 8, m = i & 255;
        t1_sh[i] = g_t1[((size_t)(b * NH + n)) * QQ + m];
    }
    __syncthreads();

    float acc[16];
#pragma unroll
    for (int b = 0; b < 16; b++) acc[b] = 0.f;
    {
        const float* u2 = u_q2 + (size_t)n * QQ * AA + a;
        int m0 = msl * 32;
        for (int m = m0; m < m0 + 32; m++) {
            float w = u2[(size_t)m * AA];
            const float* tb = t1_sh + m;
#pragma unroll
            for (int b = 0; b < 16; b++)
                acc[b] = fmaf(tb[b * 256], w, acc[b]);
        }
    }
#pragma unroll
    for (int b = 0; b < 16; b++) part[(msl * 16 + b) * 33 + ai] = acc[b];
    __syncthreads();
    {
        int bp = tid >> 5;
        float s0 = 0.f, s1 = 0.f;
#pragma unroll
        for (int s = 0; s < 8; s++) {
            s0 += part[(s * 16 + bp) * 33 + ai];
            s1 += part[(s * 16 + bp + 8) * 33 + ai];
        }
        g_cq2[((size_t)(bp * NH + n)) * AA + a] = s0;
        g_cq2[((size_t)((bp + 8) * NH + n)) * AA + a] = s1;
    }
}

// ---------------- ctx-c: scalars + hcqT write (coalesced) ------------------
__global__ __launch_bounds__(256) void k_ctx_c(const float* __restrict__ vck) {
    int bn = blockIdx.x;
    int n = bn & 7;
    int tid = threadIdx.x;

    __shared__ float cq2_sh[AA];
    __shared__ float red[256];
    __shared__ float lamq_sh;

    if (tid < AA) cq2_sh[tid] = g_cq2[(size_t)bn * AA + tid];

    red[tid] = g_hck[(size_t)bn * QQ + tid] * vck[n * QQ + tid];
    __syncthreads();
    for (int off = 128; off > 0; off >>= 1) {
        if (tid < off) red[tid] += red[tid + off];
        __syncthreads();
    }
    if (tid == 0) g_ckdot[bn] = red[0];
    __syncthreads();

    red[tid] = (tid < AA) ? cq2_sh[tid] * g_vcqsum[n * AA + tid] : 0.f;
    __syncthreads();
    for (int off = 128; off > 0; off >>= 1) {
        if (tid < off) red[tid] += red[tid + off];
        __syncthreads();
    }
    if (tid == 0) {
        float qd = 0.f;
#pragma unroll
        for (int k = 0; k < 8; k++) qd += g_qdotp[n * 8 + k];
        lamq_sh = 1.f / (1.f + __expf(-(qd + red[0])));
    }
    __syncthreads();

    float lq = lamq_sh;
    const float inv_sq = 1.f / 16.f;
    const float* qtp = g_qT + (size_t)n * AA * QQ + tid;
    __nv_bfloat16* op = g_hcqT + (size_t)bn * AA * QQ + tid;
#pragma unroll 4
    for (int a = 0; a < AA; a++) {
        float qv = qtp[(size_t)a * QQ];
        float v = (fmaf(lq, cq2_sh[a] - qv, qv)) * inv_sq;
        op[(size_t)a * QQ] = __float2bfloat16_rn(v);
    }
}

// ---------------- K3a: GEMM1 + lambda (small smem, 3 CTAs/SM) --------------
// smem: XS x-tile [64][200] bf16 (25600); W1 2x 12800; vhk 1024; lam 768
#define A_XSTR 200
#define A_XS 0
#define A_W1A 25600
#define A_W1B 38400
#define A_VHK 51200
#define A_LAMP 52224
#define A_SMEM 52992

__global__ __launch_bounds__(256, 3) void k_g1(
        const float* __restrict__ ht, const float* __restrict__ vhk) {
    extern __shared__ char smem[];
    uint32_t sb = smem_u32(smem);
    int tid = threadIdx.x;
    int w = tid >> 5, lane = tid & 31;
    int rg = w & 3, sub = w >> 2;
    int bn = blockIdx.y;
    int b = bn >> 3, n = bn & 7;
    int tile = blockIdx.x;
    int t0 = tile * 64;

    // prefetch W1 chunk 0
    {
        const uint4* wsrc = (const uint4*)(g_w1t + (size_t)n * QQ * DD);
#pragma unroll
        for (int it = 0; it < 3; it++) {
            int idx = it * 256 + tid;            // 32 rows x 24 uint4
            int row = idx / 24, c8 = idx - row * 24;
            CP_ASYNC16(sb + A_W1A + (row * A_XSTR + c8 * 8) * 2, wsrc + idx);
        }
        CP_COMMIT();
    }

    ((float*)(smem + A_VHK))[tid] = vhk[n * QQ + tid];

    // load x tile (64 x 192 fp32 -> bf16), zero-pad rows past TT
    {
        const float* xb = ht + ((size_t)b * TT + t0) * CC + n * DD;
#pragma unroll
        for (int it = 0; it < 12; it++) {
            int idx = it * 256 + tid;            // 64 rows x 48 float4
            int row = idx / 48, c4 = idx - row * 48;
            float4 v = make_float4(0.f, 0.f, 0.f, 0.f);
            if (t0 + row < TT) v = *(const float4*)(xb + (size_t)row * CC + c4 * 4);
            uint2 pk = make_uint2(pack_bf(v.x, v.y), pack_bf(v.z, v.w));
            *(uint2*)(smem + A_XS + (row * A_XSTR + c4 * 4) * 2) = pk;
        }
    }
    __syncthreads();

    uint32_t abase = sb + A_XS + ((rg * 16 + (lane & 15)) * A_XSTR + (lane >> 4) * 8) * 2;
    uint32_t boff = ((sub * 16 + (lane >> 4) * 8 + (lane & 7)) * A_XSTR
                     + ((lane >> 3) & 1) * 8) * 2;
    int r0 = rg * 16 + (lane >> 2);
    uint32_t* hkout = g_hk + (size_t)(bn * 32 + tile) * 64 * 128;
    const float* vhk_s = (const float*)(smem + A_VHK);

    float lam0 = 0.f, lam1 = 0.f;
    for (int qc = 0; qc < 8; qc++) {
        if (qc < 7) {
            int buf = ((qc + 1) & 1) ? A_W1B : A_W1A;
            const uint4* wsrc = (const uint4*)(g_w1t + ((size_t)n * QQ + (qc + 1) * 32) * DD);
#pragma unroll
            for (int it = 0; it < 3; it++) {
                int idx = it * 256 + tid;
                int row = idx / 24, c8 = idx - row * 24;
                CP_ASYNC16(sb + buf + (row * A_XSTR + c8 * 8) * 2, wsrc + idx);
            }
            CP_COMMIT();
            CP_WAIT1();
        } else {
            CP_WAIT0();
        }
        __syncthreads();

        uint32_t bbase = sb + ((qc & 1) ? A_W1B : A_W1A) + boff;

        float c[2][4];
#pragma unroll
        for (int j = 0; j < 2; j++)
#pragma unroll
            for (int e = 0; e < 4; e++) c[j][e] = 0.f;

#pragma unroll
        for (int kk = 0; kk < 12; kk++) {
            uint32_t a[4], bf[4];
            ldsm_x4(a, abase + kk * 32);
            ldsm_x4(bf, bbase + kk * 32);
            mma_bf16(c[0], a, bf[0], bf[1]);
            mma_bf16(c[1], a, bf[2], bf[3]);
        }

#pragma unroll
        for (int j = 0; j < 2; j++) {
            int col = qc * 32 + sub * 16 + j * 8 + 2 * (lane & 3);
            float v0 = vhk_s[col], v1 = vhk_s[col + 1];
            lam0 += c[j][0] * v0 + c[j][1] * v1;
            lam1 += c[j][2] * v0 + c[j][3] * v1;
            hkout[r0 * 128 + (col >> 1)] = pack_bf(c[j][0], c[j][1]);
            hkout[(r0 + 8) * 128 + (col >> 1)] = pack_bf(c[j][2], c[j][3]);
        }
        __syncthreads();   // all reads of this buffer done before re-fill
    }

    // lambda finalize
    lam0 += __shfl_xor_sync(0xffffffffu, lam0, 1);
    lam0 += __shfl_xor_sync(0xffffffffu, lam0, 2);
    lam1 += __shfl_xor_sync(0xffffffffu, lam1, 1);
    lam1 += __shfl_xor_sync(0xffffffffu, lam1, 2);
    if ((lane & 3) == 0) {
        float* lp = (float*)(smem + A_LAMP);
        lp[sub * 64 + r0] = lam0;
        lp[sub * 64 + r0 + 8] = lam1;
    }
    __syncthreads();
    if (tid < 64) {
        const float* lp = (const float*)(smem + A_LAMP);
        float s = lp[tid] + lp[64 + tid] + g_ckdot[bn];
        g_lamt[(bn * 32 + tile) * 64 + tid] = 1.f / (1.f + __expf(-s));
    }
}

// ---------------- K3b: activation + GEMM2 + fused pool ---------------------
// smem: HK k2 [64][264] bf16 (33792); RG hcq chunk [96][264] (50688); aux
#define HK_STRIDE 264
#define SS_STRIDE 100
#define B_HK 0
#define B_RG 33792
#define B_AUX 84480
#define B_HCK  (B_AUX + 0)
#define B_KBV  (B_AUX + 1024)
#define B_GRS  (B_AUX + 2048)
#define B_BETA (B_AUX + 3072)
#define B_QB   (B_AUX + 4096)
#define B_LAMS (B_AUX + 4864)
#define B_SMEM (B_AUX + 5120)

__global__ __launch_bounds__(256, 2) void k_g2(
        const float* __restrict__ ht, const float* __restrict__ kb,
        const float* __restrict__ bg, const float* __restrict__ bbias,
        const float* __restrict__ bm, const float* __restrict__ bv,
        const float* __restrict__ qb) {
    extern __shared__ char smem[];
    uint32_t sb = smem_u32(smem);
    int tid = threadIdx.x;
    int w = tid >> 5, lane = tid & 31;
    int rg = w & 3, sub = w >> 2;
    int bn = blockIdx.y;
    int b = bn >> 3, n = bn & 7;
    int tile = blockIdx.x;
    int t0 = tile * 64;

    // group 0: k2 (raw hk) tile -> HK smem   (64 rows x 32 uint4)
    {
        const uint4* src = (const uint4*)(g_hk + (size_t)(bn * 32 + tile) * 64 * 128);
#pragma unroll
        for (int it = 0; it < 8; it++) {
            int idx = it * 256 + tid;
            int row = idx >> 5, c8 = idx & 31;
            CP_ASYNC16(sb + B_HK + (row * HK_STRIDE + c8 * 8) * 2, src + idx);
        }
        CP_COMMIT();
    }
    // group 1: hcq chunk 0 (96 rows x 32 uint4) -> RG
    {
        const uint4* hs = (const uint4*)(g_hcqT + (size_t)bn * AA * QQ);
#pragma unroll
        for (int it = 0; it < 12; it++) {
            int idx = it * 256 + tid;
            int row = idx / 32, c8 = idx - row * 32;
            CP_ASYNC16(sb + B_RG + (row * HK_STRIDE + c8 * 8) * 2, hs + idx);
        }
        CP_COMMIT();
    }

    // aux constants
    {
        int i = tid;
        float g = bg[i];
        float grs = g * rsqrtf(bv[i] + 1e-5f);
        ((float*)(smem + B_GRS))[i] = grs;
        ((float*)(smem + B_BETA))[i] = bbias[i] - grs * bm[i];
        ((float*)(smem + B_HCK))[i] = g_hck[(size_t)bn * QQ + i];
        ((float*)(smem + B_KBV))[i] = kb[n * QQ + i];
        if (i < AA) ((float*)(smem + B_QB))[i] = qb[n * AA + i];
        if (i < 64) ((float*)(smem + B_LAMS))[i] = g_lamt[(bn * 32 + tile) * 64 + i];
    }

    CP_WAIT1();   // k2 resident
    __syncthreads();

    // ---- activation in place on HK ----
    {
        int row = tid >> 2;
        int cb = (tid & 3) * 64;
        float lam = ((const float*)(smem + B_LAMS))[row];
        const float* hck_s = (const float*)(smem + B_HCK);
        const float* kbv_s = (const float*)(smem + B_KBV);
        const float* grs_s = (const float*)(smem + B_GRS);
        const float* bet_s = (const float*)(smem + B_BETA);
        uint32_t* hp = (uint32_t*)(smem + B_HK + (row * HK_STRIDE + cb) * 2);
#pragma unroll
        for (int j = 0; j < 8; j++) {
            uint4 v = *(uint4*)(hp + j * 4);
            uint32_t* vr = (uint32_t*)&v;
#pragma unroll
            for (int e = 0; e < 4; e++) {
                int c0 = cb + j * 8 + 2 * e;
                float h0 = bflo(vr[e]), h1 = bfhi(vr[e]);
                float m0 = fmaf(lam, hck_s[c0] - h0, h0) + kbv_s[c0];
                float m1 = fmaf(lam, hck_s[c0 + 1] - h1, h1) + kbv_s[c0 + 1];
                m0 = fmaxf(m0, 0.f); m1 = fmaxf(m1, 0.f);
                float a0 = tanha(fmaf(grs_s[c0], m0, bet_s[c0]));
                float a1 = tanha(fmaf(grs_s[c0 + 1], m1, bet_s[c0 + 1]));
                vr[e] = pack_bf(a0, a1);
            }
            *(uint4*)(hp + j * 4) = v;
        }
    }
    CP_WAIT0();   // hcq chunk 0 resident
    __syncthreads();

    // ---- GEMM2: 2 a-chunks of 96; both fragment sets in registers ----
    uint32_t abase2 = sb + B_HK + ((rg * 16 + (lane & 15)) * HK_STRIDE + (lane >> 4) * 8) * 2;
    uint32_t boff_hcq = ((sub * 48 + (lane >> 4) * 8 + (lane & 7)) * HK_STRIDE
                         + ((lane >> 3) & 1) * 8) * 2;
    int r0 = rg * 16 + (lane >> 2);

    float c2a[3][2][4], c2b[3][2][4];
#pragma unroll
    for (int p = 0; p < 3; p++)
#pragma unroll
        for (int j = 0; j < 2; j++)
#pragma unroll
            for (int e = 0; e < 4; e++) { c2a[p][j][e] = 0.f; c2b[p][j][e] = 0.f; }

#pragma unroll 4
    for (int kk = 0; kk < 16; kk++) {
        uint32_t a[4];
        ldsm_x4(a, abase2 + kk * 32);
#pragma unroll
        for (int p = 0; p < 3; p++) {
            uint32_t bf[4];
            ldsm_x4(bf, sb + B_RG + boff_hcq + p * 16 * HK_STRIDE * 2 + kk * 32);
            mma_bf16(c2a[p][0], a, bf[0], bf[1]);
            mma_bf16(c2a[p][1], a, bf[2], bf[3]);
        }
    }
    __syncthreads();   // chunk-0 hcq reads done

    // load hcq chunk 1
    {
        const uint4* hs = (const uint4*)(g_hcqT + ((size_t)bn * AA + 96) * QQ);
#pragma unroll
        for (int it = 0; it < 12; it++) {
            int idx = it * 256 + tid;
            int row = idx / 32, c8 = idx - row * 32;
            CP_ASYNC16(sb + B_RG + (row * HK_STRIDE + c8 * 8) * 2, hs + idx);
        }
        CP_COMMIT();
        CP_WAIT0();
    }
    __syncthreads();

#pragma unroll 4
    for (int kk = 0; kk < 16; kk++) {
        uint32_t a[4];
        ldsm_x4(a, abase2 + kk * 32);
#pragma unroll
        for (int p = 0; p < 3; p++) {
            uint32_t bf[4];
            ldsm_x4(bf, sb + B_RG + boff_hcq + p * 16 * HK_STRIDE * 2 + kk * 32);
            mma_bf16(c2b[p][0], a, bf[0], bf[1]);
            mma_bf16(c2b[p][1], a, bf[2], bf[3]);
        }
    }
    __syncthreads();   // hcq region + HK (k2) now fully dead

    // dump fragments: chunk0 -> RG region, chunk1 -> HK region
    {
        float* d0 = (float*)(smem + B_RG);
        float* d1 = (float*)(smem + B_HK);
#pragma unroll
        for (int p = 0; p < 3; p++) {
#pragma unroll
            for (int j = 0; j < 2; j++) {
                int col = sub * 48 + p * 16 + j * 8 + 2 * (lane & 3);
                *(float2*)(d0 + r0 * SS_STRIDE + col) = make_float2(c2a[p][j][0], c2a[p][j][1]);
                *(float2*)(d0 + (r0 + 8) * SS_STRIDE + col) = make_float2(c2a[p][j][2], c2a[p][j][3]);
                *(float2*)(d1 + r0 * SS_STRIDE + col) = make_float2(c2b[p][j][0], c2b[p][j][1]);
                *(float2*)(d1 + (r0 + 8) * SS_STRIDE + col) = make_float2(c2b[p][j][2], c2b[p][j][3]);
            }
        }
    }
    __syncthreads();

    // ---- fused softmax partials: thread == a (192 active) -----------------
    if (tid < AA) {
        int a = tid;
        const float* ssm = (a < 96) ? (const float*)(smem + B_RG)
                                    : (const float*)(smem + B_HK);
        int acol = (a < 96) ? a : (a - 96);
        float qbv = ((const float*)(smem + B_QB))[a];
        int tmax = TT - t0; if (tmax > 64) tmax = 64;

        float M = -1e30f;
        for (int t = 0; t < tmax; t++)
            M = fmaxf(M, ssm[t * SS_STRIDE + acol]);
        M += qbv;

        float Z = 0.f, S1 = 0.f, S2 = 0.f;
        const float* vp = ht + ((size_t)b * TT + t0) * CC + n * DD + a;
#pragma unroll 4
        for (int t = 0; t < tmax; t++) {
            float s = ssm[t * SS_STRIDE + acol] + qbv;
            float wv = __expf(s - M);
            float v = vp[(size_t)t * CC];
            Z += wv; S1 += wv * v; S2 += wv * v * v;
        }
        g_pp[((size_t)bn * 32 + tile) * AA + a] = make_float4(M, Z, S1, S2);
    }
}

// ---------------- K4: merge 32 tile partials -> output ---------------------
__global__ __launch_bounds__(192) void k_pool_merge(float* __restrict__ out) {
    int bn = blockIdx.x;
    int b = bn >> 3, n = bn & 7;
    int a = threadIdx.x;

    const float4* pp = g_pp + (size_t)bn * 32 * AA + a;
    float M = -1e30f;
#pragma unroll
    for (int s = 0; s < 32; s++) M = fmaxf(M, pp[s * AA].x);
    float Zt = 0.f, S1t = 0.f, S2t = 0.f;
#pragma unroll
    for (int s = 0; s < 32; s++) {
        float4 p = pp[s * AA];
        float c = __expf(p.x - M);
        Zt += p.y * c; S1t += p.z * c; S2t += p.w * c;
    }
    float mu = S1t / Zt;
    float ex2 = S2t / Zt;
    float rh = sqrtf(fmaxf(ex2 - mu * mu, 1e-9f));
    out[(size_t)b * (2 * CC) + n * DD + a] = mu;
    out[(size_t)b * (2 * CC) + CC + n * DD + a] = rh;
}

// ---------------- launcher ------------------------------------------------
extern "C" void kernel_launch(void* const* d_in, const int* in_sizes, int n_in,
                              void* d_out, int out_size) {
    const float* ht       = (const float*)d_in[0];
    const float* k_proj_W = (const float*)d_in[1];
    const float* query    = (const float*)d_in[2];
    const float* uk_W     = (const float*)d_in[3];
    const float* u_q1W    = (const float*)d_in[4];
    const float* u_q2     = (const float*)d_in[5];
    const float* vhq      = (const float*)d_in[6];
    const float* vhk      = (const float*)d_in[7];
    const float* vcq      = (const float*)d_in[8];
    const float* vck      = (const float*)d_in[9];
    const float* k_proj_b = (const float*)d_in[10];
    const float* q_b      = (const float*)d_in[11];
    const float* u_q1b    = (const float*)d_in[12];
    const float* bnc_g    = (const float*)d_in[13];
    const float* bnc_b    = (const float*)d_in[14];
    const float* bnc_m    = (const float*)d_in[15];
    const float* bnc_v    = (const float*)d_in[16];
    const float* bnk_g    = (const float*)d_in[17];
    const float* bnk_b    = (const float*)d_in[18];
    const float* bnk_m    = (const float*)d_in[19];
    const float* bnk_v    = (const float*)d_in[20];
    float* out = (float*)d_out;

    static int smem_set = 0;
    if (!smem_set) {
        cudaFuncSetAttribute(k_g1, cudaFuncAttributeMaxDynamicSharedMemorySize, A_SMEM);
        cudaFuncSetAttribute(k_g2, cudaFuncAttributeMaxDynamicSharedMemorySize, B_SMEM);
        smem_set = 1;
    }

    dim3 gs(CC / 128, BB);
    dim3 bs(128, 8);
    k_stats<<<gs, bs>>>(ht);

    dim3 gt(48, NH), bt(32, 8);
    k_prepw<<<gt, bt>>>(k_proj_W);
    k_prepq<<<gt, bt>>>(query);
    dim3 gq(8, NH);
    k_qdot<<<gq, 256>>>(query, vhq, vcq);

    dim3 ga(8, NH);
    k_ctx_a<<<ga, 256>>>(uk_W, u_q1W, u_q1b, bnc_g, bnc_b, bnc_m, bnc_v);
    dim3 gb(6, NH);
    k_ctx_b<<<gb, 256>>>(u_q2);
    k_ctx_c<<<BB * NH, 256>>>(vck);

    dim3 gsc(32, BB * NH);   // 32 t-tiles of 64 x 128 (b,n)
    k_g1<<<gsc, 256, A_SMEM>>>(ht, vhk);
    k_g2<<<gsc, 256, B_SMEM>>>(ht, k_proj_b, bnk_g, bnk_b, bnk_m, bnk_v, q_b);

    k_pool_merge<<<BB * NH, AA>>>(out);
}

// round 12
// speedup vs baseline: 1.2734x; 1.2734x over previous
#include <cuda_runtime.h>
#include <cuda_bf16.h>
#include <math.h>
#include <stdint.h>

// Problem constants
#define BB 16
#define TT 2000
#define CC 1536
#define NH 8
#define DD 192
#define QQ 256
#define AA 192

// ===================== warp-MMA helpers (sm_80+ baseline) ==================
__device__ __forceinline__ uint32_t smem_u32(const void* p) {
    uint32_t a;
    asm("{ .reg .u64 t; cvta.to.shared.u64 t, %1; cvt.u32.u64 %0, t; }"
        : "=r"(a) : "l"(p));
    return a;
}
__device__ __forceinline__ void ldsm_x4(uint32_t r[4], uint32_t addr) {
    asm volatile("ldmatrix.sync.aligned.m8n8.x4.shared.b16 {%0,%1,%2,%3}, [%4];"
                 : "=r"(r[0]), "=r"(r[1]), "=r"(r[2]), "=r"(r[3]) : "r"(addr));
}
__device__ __forceinline__ void mma_bf16(float c[4], const uint32_t a[4],
                                         uint32_t b0, uint32_t b1) {
    asm volatile("mma.sync.aligned.m16n8k16.row.col.f32.bf16.bf16.f32 "
                 "{%0,%1,%2,%3}, {%4,%5,%6,%7}, {%8,%9}, {%0,%1,%2,%3};"
                 : "+f"(c[0]), "+f"(c[1]), "+f"(c[2]), "+f"(c[3])
                 : "r"(a[0]), "r"(a[1]), "r"(a[2]), "r"(a[3]), "r"(b0), "r"(b1));
}
__device__ __forceinline__ uint32_t pack_bf(float lo, float hi) {
    uint32_t r;
    asm("cvt.rn.bf16x2.f32 %0, %1, %2;" : "=r"(r) : "f"(hi), "f"(lo));
    return r;
}
__device__ __forceinline__ float bflo(uint32_t u) { return __uint_as_float(u << 16); }
__device__ __forceinline__ float bfhi(uint32_t u) { return __uint_as_float(u & 0xffff0000u); }
__device__ __forceinline__ float tanha(float x) {
    float r; asm("tanh.approx.f32 %0, %1;" : "=f"(r) : "f"(x)); return r;
}
#define CP_ASYNC16(dst, src) \
    asm volatile("cp.async.cg.shared.global [%0], [%1], 16;" :: "r"(dst), "l"(src))
#define CP_COMMIT() asm volatile("cp.async.commit_group;" ::: "memory")
#define CP_WAIT0() asm volatile("cp.async.wait_group 0;" ::: "memory")
#define CP_WAIT1() asm volatile("cp.async.wait_group 1;" ::: "memory")

// ---------------- scratch (device globals: no allocations allowed) --------
__device__ float g_c[BB * CC * 2];
__device__ float g_hck[BB * NH * QQ];
__device__ float g_t1[BB * NH * QQ];
__device__ float g_cq2[BB * NH * AA];
__device__ float g_vcqsum[NH * AA];
__device__ float g_ckdot[BB * NH];
__device__ float g_qdotp[NH * 8];
__device__ float g_qT[NH * AA * QQ];                          // query^T [n][a][q]
__device__ __nv_bfloat16 g_w1t[NH * QQ * DD];                 // W1^T [n][q][d] bf16
__device__ __nv_bfloat16 g_hcqT[(size_t)BB * NH * AA * QQ];   // hcq^T/sqrt(Q) [bn][a][q]
__device__ float4 g_pp[BB * NH * 16 * AA];                    // pool partials per tile

// ---------------- K1: mean/std over time ----------------------------------
__global__ void k_stats(const float* __restrict__ ht) {
    int b = blockIdx.y;
    int ch = blockIdx.x * 128 + threadIdx.x;
    int ty = threadIdx.y;
    float s = 0.f, s2 = 0.f;
    const float* p = ht + (size_t)b * TT * CC + ch;
    for (int t = ty; t < TT; t += 8) {
        float v = p[(size_t)t * CC];
        s += v; s2 += v * v;
    }
    __shared__ float sh0[8][128];
    __shared__ float sh1[8][128];
    sh0[ty][threadIdx.x] = s;
    sh1[ty][threadIdx.x] = s2;
    __syncthreads();
    if (ty == 0) {
        for (int j = 1; j < 8; j++) { s += sh0[j][threadIdx.x]; s2 += sh1[j][threadIdx.x]; }
        float mean = s * (1.f / TT);
        float var = (s2 - (float)TT * mean * mean) * (1.f / (TT - 1));
        float sd = sqrtf(fmaxf(var, 0.f));
        g_c[((size_t)b * CC + ch) * 2 + 0] = mean;
        g_c[((size_t)b * CC + ch) * 2 + 1] = sd;
    }
}

// ---------------- K0: qdot partials + vcq_sum (coalesced via g_qT) ---------
__global__ void k_qdot(const float* __restrict__ query, const float* __restrict__ vhq,
                       const float* __restrict__ vcq) {
    int s = blockIdx.x;
    int n = blockIdx.y;
    int tid = threadIdx.x;
    (void)query;
    float acc = 0.f;
    int base = s * (AA * QQ / 8);
    const float* qt = g_qT + (size_t)n * AA * QQ;
    const float* vh = vhq + (size_t)n * AA * QQ;
    for (int ii = tid; ii < AA * QQ / 8; ii += 256) {
        int i = base + ii;                 // i = a*QQ + q; both operands contiguous
        acc += qt[i] * vh[i];
    }
    __shared__ float red[256];
    red[tid] = acc;
    __syncthreads();
    for (int off = 128; off > 0; off >>= 1) {
        if (tid < off) red[tid] += red[tid + off];
        __syncthreads();
    }
    if (tid == 0) g_qdotp[n * 8 + s] = red[0];

    int w = tid >> 5, lane = tid & 31;
    for (int r = w; r < AA / 8; r += 8) {
        int a = s * (AA / 8) + r;
        const float* vp = vcq + ((size_t)n * AA + a) * QQ;
        float sum = 0.f;
        for (int q = lane; q < QQ; q += 32) sum += vp[q];
#pragma unroll
        for (int o = 16; o > 0; o >>= 1) sum += __shfl_down_sync(0xffffffffu, sum, o);
        if (lane == 0) g_vcqsum[n * AA + a] = sum;
    }
}

// ---------------- prep: W1^T -> bf16 (tiled transpose) ---------------------
__global__ void k_prepw(const float* __restrict__ W1) {
    int n = blockIdx.y;
    int tile = blockIdx.x;
    int d0 = (tile % 6) * 32, q0 = (tile / 6) * 32;
    int tx = threadIdx.x, ty = threadIdx.y;
    __shared__ float tl[32][33];
#pragma unroll
    for (int j = 0; j < 4; j++)
        tl[ty + j * 8][tx] = W1[((size_t)n * DD + d0 + ty + j * 8) * QQ + q0 + tx];
    __syncthreads();
#pragma unroll
    for (int j = 0; j < 4; j++)
        g_w1t[((size_t)n * QQ + q0 + ty + j * 8) * DD + d0 + tx] =
            __float2bfloat16_rn(tl[tx][ty + j * 8]);
}

// ---------------- prep: query^T fp32 (tiled transpose) ---------------------
__global__ void k_prepq(const float* __restrict__ query) {
    int n = blockIdx.y;
    int tile = blockIdx.x;
    int a0 = (tile % 6) * 32, q0 = (tile / 6) * 32;
    int tx = threadIdx.x, ty = threadIdx.y;
    __shared__ float tl[32][33];
#pragma unroll
    for (int j = 0; j < 4; j++)
        tl[ty + j * 8][tx] = query[((size_t)n * QQ + q0 + ty + j * 8) * AA + a0 + tx];
    __syncthreads();
#pragma unroll
    for (int j = 0; j < 4; j++)
        g_qT[((size_t)n * AA + a0 + ty + j * 8) * QQ + q0 + tx] = tl[tx][ty + j * 8];
}

// ---------------- ctx-a: hck + t1 for all 16 b per block -------------------
__global__ __launch_bounds__(256) void k_ctx_a(
        const float* __restrict__ uk_W, const float* __restrict__ u_q1W,
        const float* __restrict__ u_q1b,
        const float* __restrict__ bnc_g, const float* __restrict__ bnc_b,
        const float* __restrict__ bnc_m, const float* __restrict__ bnc_v) {
    int n = blockIdx.y, qt = blockIdx.x;
    int tid = threadIdx.x;
    int qi = tid & 31, sl = tid >> 5;
    int q = qt * 32 + qi;

    __shared__ float c_sh[16 * 384];
    __shared__ float part[8 * 16 * 33];

    for (int i = tid; i < 16 * 384; i += 256) {
        int b = i / 384, l = i - b * 384;
        c_sh[i] = g_c[((size_t)b * CC + n * DD) * 2 + l];
    }
    __syncthreads();

    float ak[16], aq[16];
#pragma unroll
    for (int b = 0; b < 16; b++) { ak[b] = 0.f; aq[b] = 0.f; }
    {
        const float* uk = uk_W + ((size_t)n * 384) * QQ + q;
        const float* u1 = u_q1W + ((size_t)n * 384) * QQ + q;
        int l0 = sl * 48;
        for (int l = l0; l < l0 + 48; l++) {
            float wk = uk[(size_t)l * QQ];
            float w1 = u1[(size_t)l * QQ];
            const float* cb = c_sh + l;
#pragma unroll
            for (int b = 0; b < 16; b++) {
                float cv = cb[b * 384];
                ak[b] = fmaf(cv, wk, ak[b]);
                aq[b] = fmaf(cv, w1, aq[b]);
            }
        }
    }

#pragma unroll
    for (int b = 0; b < 16; b++) part[(sl * 16 + b) * 33 + qi] = ak[b];
    __syncthreads();
    {
        int bp = tid >> 5;
        float s0 = 0.f, s1 = 0.f;
#pragma unroll
        for (int s = 0; s < 8; s++) {
            s0 += part[(s * 16 + bp) * 33 + qi];
            s1 += part[(s * 16 + bp + 8) * 33 + qi];
        }
        g_hck[((size_t)(bp * NH + n)) * QQ + q] = s0;
        g_hck[((size_t)((bp + 8) * NH + n)) * QQ + q] = s1;
    }
    __syncthreads();

#pragma unroll
    for (int b = 0; b < 16; b++) part[(sl * 16 + b) * 33 + qi] = aq[b];
    __syncthreads();
    {
        int bp = tid >> 5;
        float s0 = 0.f, s1 = 0.f;
#pragma unroll
        for (int s = 0; s < 8; s++) {
            s0 += part[(s * 16 + bp) * 33 + qi];
            s1 += part[(s * 16 + bp + 8) * 33 + qi];
        }
        float bias = u_q1b[n * QQ + q];
        float grs = bnc_g[q] * rsqrtf(bnc_v[q] + 1e-5f);
        float beta = bnc_b[q] - grs * bnc_m[q];
        float r0 = fmaxf(s0 + bias, 0.f);
        float r1 = fmaxf(s1 + bias, 0.f);
        g_t1[((size_t)(bp * NH + n)) * QQ + q] = tanhf(fmaf(grs, r0, beta));
        g_t1[((size_t)((bp + 8) * NH + n)) * QQ + q] = tanhf(fmaf(grs, r1, beta));
    }
}

// ---------------- ctx-b: cq2 = t1 @ u_q2 for all 16 b per block ------------
__global__ __launch_bounds__(256) void k_ctx_b(const float* __restrict__ u_q2) {
    int n = blockIdx.y, at = blockIdx.x;
    int tid = threadIdx.x;
    int ai = tid & 31, msl = tid >> 5;
    int a = at * 32 + ai;

    __shared__ float t1_sh[16 * 256];
    __shared__ float part[8 * 16 * 33];

    for (int i = tid; i < 16 * 256; i += 256) {
        int b = i >> 8, m = i & 255;
        t1_sh[i] = g_t1[((size_t)(b * NH + n)) * QQ + m];
    }
    __syncthreads();

    float acc[16];
#pragma unroll
    for (int b = 0; b < 16; b++) acc[b] = 0.f;
    {
        const float* u2 = u_q2 + (size_t)n * QQ * AA + a;
        int m0 = msl * 32;
        for (int m = m0; m < m0 + 32; m++) {
            float w = u2[(size_t)m * AA];
            const float* tb = t1_sh + m;
#pragma unroll
            for (int b = 0; b < 16; b++)
                acc[b] = fmaf(tb[b * 256], w, acc[b]);
        }
    }
#pragma unroll
    for (int b = 0; b < 16; b++) part[(msl * 16 + b) * 33 + ai] = acc[b];
    __syncthreads();
    {
        int bp = tid >> 5;
        float s0 = 0.f, s1 = 0.f;
#pragma unroll
        for (int s = 0; s < 8; s++) {
            s0 += part[(s * 16 + bp) * 33 + ai];
            s1 += part[(s * 16 + bp + 8) * 33 + ai];
        }
        g_cq2[((size_t)(bp * NH + n)) * AA + a] = s0;
        g_cq2[((size_t)((bp + 8) * NH + n)) * AA + a] = s1;
    }
}

// ---------------- ctx-c: scalars + hcqT write (coalesced) ------------------
__global__ __launch_bounds__(256) void k_ctx_c(const float* __restrict__ vck) {
    int bn = blockIdx.x;
    int n = bn & 7;
    int tid = threadIdx.x;

    __shared__ float cq2_sh[AA];
    __shared__ float red[256];
    __shared__ float lamq_sh;

    if (tid < AA) cq2_sh[tid] = g_cq2[(size_t)bn * AA + tid];

    red[tid] = g_hck[(size_t)bn * QQ + tid] * vck[n * QQ + tid];
    __syncthreads();
    for (int off = 128; off > 0; off >>= 1) {
        if (tid < off) red[tid] += red[tid + off];
        __syncthreads();
    }
    if (tid == 0) g_ckdot[bn] = red[0];
    __syncthreads();

    red[tid] = (tid < AA) ? cq2_sh[tid] * g_vcqsum[n * AA + tid] : 0.f;
    __syncthreads();
    for (int off = 128; off > 0; off >>= 1) {
        if (tid < off) red[tid] += red[tid + off];
        __syncthreads();
    }
    if (tid == 0) {
        float qd = 0.f;
#pragma unroll
        for (int k = 0; k < 8; k++) qd += g_qdotp[n * 8 + k];
        lamq_sh = 1.f / (1.f + __expf(-(qd + red[0])));
    }
    __syncthreads();

    float lq = lamq_sh;
    const float inv_sq = 1.f / 16.f;
    const float* qtp = g_qT + (size_t)n * AA * QQ + tid;
    __nv_bfloat16* op = g_hcqT + (size_t)bn * AA * QQ + tid;
#pragma unroll 4
    for (int a = 0; a < AA; a++) {
        float qv = qtp[(size_t)a * QQ];
        float v = (fmaf(lq, cq2_sh[a] - qv, qv)) * inv_sq;
        op[(size_t)a * QQ] = __float2bfloat16_rn(v);
    }
}

// ---------------- K3: fused scores + softmax-partial kernel ----------------
#define XS_STRIDE 200
#define HK_STRIDE 264
#define SS_STRIDE 100
#define SM_XS 0
#define SM_HK 51200
#define SM_W1A 118784
#define SM_W1B 144384
#define SM_AUX 169984
#define AXH_HCK  (SM_AUX + 0)
#define AXH_KBV  (SM_AUX + 1024)
#define AXH_GRS  (SM_AUX + 2048)
#define AXH_BETA (SM_AUX + 3072)
#define AXH_VHK  (SM_AUX + 4096)
#define AXH_QB   (SM_AUX + 5120)
#define AXH_LAM  (SM_AUX + 6144)
#define SMEM_SC  (SM_AUX + 6656)

__global__ __launch_bounds__(256) void k_scores_mma(
        const float* __restrict__ ht, const float* __restrict__ kb,
        const float* __restrict__ bg, const float* __restrict__ bbias,
        const float* __restrict__ bm, const float* __restrict__ bv,
        const float* __restrict__ vhk, const float* __restrict__ qb) {
    extern __shared__ char smem[];
    uint32_t sb = smem_u32(smem);
    int tid = threadIdx.x;
    int w = tid >> 5, lane = tid & 31;
    int bn = blockIdx.y;
    int b = bn >> 3, n = bn & 7;
    int t0 = blockIdx.x * 128;

    // kick off W1 chunk 0 async load immediately
    {
        const uint4* wsrc = (const uint4*)(g_w1t + (size_t)n * QQ * DD);
#pragma unroll
        for (int it = 0; it < 6; it++) {
            int idx = it * 256 + tid;
            int row = idx / 24, c8 = idx - row * 24;
            CP_ASYNC16(sb + SM_W1A + (row * XS_STRIDE + c8 * 8) * 2, wsrc + idx);
        }
        CP_COMMIT();
    }

    // aux constant arrays
    {
        int i = tid;
        float g = bg[i];
        float grs = g * rsqrtf(bv[i] + 1e-5f);
        ((float*)(smem + AXH_GRS))[i] = grs;
        ((float*)(smem + AXH_BETA))[i] = bbias[i] - grs * bm[i];
        ((float*)(smem + AXH_HCK))[i] = g_hck[(size_t)bn * QQ + i];
        ((float*)(smem + AXH_KBV))[i] = kb[n * QQ + i];
        ((float*)(smem + AXH_VHK))[i] = vhk[n * QQ + i];
        if (i < AA) ((float*)(smem + AXH_QB))[i] = qb[n * AA + i];
    }

    // ---- load x tile (fp32 -> bf16), rows padded with zeros past TT ----
    {
        const float* xb = ht + ((size_t)b * TT + t0) * CC + n * DD;
        for (int it = 0; it < 24; it++) {
            int idx = it * 256 + tid;
            int row = idx / 48, c4 = idx - row * 48;
            float4 v = make_float4(0.f, 0.f, 0.f, 0.f);
            if (t0 + row < TT) v = *(const float4*)(xb + (size_t)row * CC + c4 * 4);
            uint2 pk = make_uint2(pack_bf(v.x, v.y), pack_bf(v.z, v.w));
            *(uint2*)(smem + SM_XS + (row * XS_STRIDE + c4 * 4) * 2) = pk;
        }
    }

    uint32_t abase = sb + SM_XS + ((w * 16 + (lane & 15)) * XS_STRIDE + (lane >> 4) * 8) * 2;
    uint32_t boff_w1 = (((lane >> 4) * 8 + (lane & 7)) * XS_STRIDE + ((lane >> 3) & 1) * 8) * 2;

    // ---- GEMM1 over 4 q-chunks of 64, double-buffered W1; lambda in regs --
    float lam0 = 0.f, lam1 = 0.f;
    for (int qc = 0; qc < 4; qc++) {
        if (qc < 3) {
            int buf = ((qc + 1) & 1) ? SM_W1B : SM_W1A;
            const uint4* wsrc = (const uint4*)(g_w1t + ((size_t)n * QQ + (qc + 1) * 64) * DD);
#pragma unroll
            for (int it = 0; it < 6; it++) {
                int idx = it * 256 + tid;
                int row = idx / 24, c8 = idx - row * 24;
                CP_ASYNC16(sb + buf + (row * XS_STRIDE + c8 * 8) * 2, wsrc + idx);
            }
            CP_COMMIT();
            CP_WAIT1();
        } else {
            CP_WAIT0();
        }
        __syncthreads();

        uint32_t bbase = sb + ((qc & 1) ? SM_W1B : SM_W1A) + boff_w1;

        float c[4][2][4];
#pragma unroll
        for (int p = 0; p < 4; p++)
#pragma unroll
            for (int j = 0; j < 2; j++)
#pragma unroll
                for (int e = 0; e < 4; e++) c[p][j][e] = 0.f;

        for (int kk = 0; kk < 12; kk++) {
            uint32_t a[4];
            ldsm_x4(a, abase + kk * 32);
#pragma unroll
            for (int p = 0; p < 4; p++) {
                uint32_t bf[4];
                ldsm_x4(bf, bbase + p * 16 * XS_STRIDE * 2 + kk * 32);
                mma_bf16(c[p][0], a, bf[0], bf[1]);
                mma_bf16(c[p][1], a, bf[2], bf[3]);
            }
        }

        const float* vhk_s = (const float*)(smem + AXH_VHK);
        int r0 = w * 16 + (lane >> 2);
#pragma unroll
        for (int p = 0; p < 4; p++) {
#pragma unroll
            for (int j = 0; j < 2; j++) {
                int col = qc * 64 + p * 16 + j * 8 + 2 * (lane & 3);
                float v0 = vhk_s[col], v1 = vhk_s[col + 1];
                lam0 += c[p][j][0] * v0 + c[p][j][1] * v1;
                lam1 += c[p][j][2] * v0 + c[p][j][3] * v1;
                *(uint32_t*)(smem + SM_HK + (r0 * HK_STRIDE + col) * 2) =
                    pack_bf(c[p][j][0], c[p][j][1]);
                *(uint32_t*)(smem + SM_HK + ((r0 + 8) * HK_STRIDE + col) * 2) =
                    pack_bf(c[p][j][2], c[p][j][3]);
            }
        }
        __syncthreads();
    }

    // prefetch hcq chunk 0 into XS region (xs dead after GEMM1)
    {
        const uint4* hs = (const uint4*)(g_hcqT + (size_t)bn * AA * QQ);
#pragma unroll
        for (int it = 0; it < 12; it++) {
            int idx = it * 256 + tid;
            int row = idx / 32, c8 = idx - row * 32;
            CP_ASYNC16(sb + SM_XS + (row * HK_STRIDE + c8 * 8) * 2, hs + idx);
        }
        CP_COMMIT();
    }

    // lambda finalize
    lam0 += __shfl_xor_sync(0xffffffffu, lam0, 1);
    lam0 += __shfl_xor_sync(0xffffffffu, lam0, 2);
    lam1 += __shfl_xor_sync(0xffffffffu, lam1, 1);
    lam1 += __shfl_xor_sync(0xffffffffu, lam1, 2);
    {
        float ckd = g_ckdot[bn];
        if ((lane & 3) == 0) {
            float* lam_sh = (float*)(smem + AXH_LAM);
            lam_sh[w * 16 + (lane >> 2)] = 1.f / (1.f + __expf(-(lam0 + ckd)));
            lam_sh[w * 16 + (lane >> 2) + 8] = 1.f / (1.f + __expf(-(lam1 + ckd)));
        }
    }
    __syncthreads();

    // ---- activation in place (overlaps hcq chunk0 cp.async) ----
    {
        int row = w * 16 + (lane >> 1);
        int cb = (lane & 1) * 128;
        float lam = ((const float*)(smem + AXH_LAM))[row];
        const float* hck_s = (const float*)(smem + AXH_HCK);
        const float* kbv_s = (const float*)(smem + AXH_KBV);
        const float* grs_s = (const float*)(smem + AXH_GRS);
        const float* bet_s = (const float*)(smem + AXH_BETA);
        uint32_t* hp = (uint32_t*)(smem + SM_HK + (row * HK_STRIDE + cb) * 2);
        for (int j = 0; j < 16; j++) {
            uint4 v = *(uint4*)(hp + j * 4);
            uint32_t* vr = (uint32_t*)&v;
#pragma unroll
            for (int e = 0; e < 4; e++) {
                int c0 = cb + j * 8 + 2 * e;
                float h0 = bflo(vr[e]), h1 = bfhi(vr[e]);
                float m0 = fmaf(lam, hck_s[c0] - h0, h0) + kbv_s[c0];
                float m1 = fmaf(lam, hck_s[c0 + 1] - h1, h1) + kbv_s[c0 + 1];
                m0 = fmaxf(m0, 0.f); m1 = fmaxf(m1, 0.f);
                float a0 = tanha(fmaf(grs_s[c0], m0, bet_s[c0]));
                float a1 = tanha(fmaf(grs_s[c0 + 1], m1, bet_s[c0 + 1]));
                vr[e] = pack_bf(a0, a1);
            }
            *(uint4*)(hp + j * 4) = v;
        }
    }

    // ---- GEMM2 over 2 a-chunks of 96; fragments -> fp32 smem --------------
    uint32_t abase2 = sb + SM_HK + ((w * 16 + (lane & 15)) * HK_STRIDE + (lane >> 4) * 8) * 2;
    uint32_t boff_hcq = (((lane >> 4) * 8 + (lane & 7)) * HK_STRIDE + ((lane >> 3) & 1) * 8) * 2;
    int r0 = w * 16 + (lane >> 2);

    for (int ac = 0; ac < 2; ac++) {
        if (ac == 0) {
            const uint4* hs = (const uint4*)(g_hcqT + ((size_t)bn * AA + 96) * QQ);
#pragma unroll
            for (int it = 0; it < 12; it++) {
                int idx = it * 256 + tid;
                int row = idx / 32, c8 = idx - row * 32;
                CP_ASYNC16(sb + SM_W1A + (row * HK_STRIDE + c8 * 8) * 2, hs + idx);
            }
            CP_COMMIT();
            CP_WAIT1();
        } else {
            CP_WAIT0();
        }
        __syncthreads();

        uint32_t bbase2 = sb + (ac ? SM_W1A : SM_XS) + boff_hcq;

        float c2[6][2][4];
#pragma unroll
        for (int p = 0; p < 6; p++)
#pragma unroll
            for (int j = 0; j < 2; j++)
#pragma unroll
                for (int e = 0; e < 4; e++) c2[p][j][e] = 0.f;

        for (int kk = 0; kk < 16; kk++) {
            uint32_t a[4];
            ldsm_x4(a, abase2 + kk * 32);
#pragma unroll
            for (int p = 0; p < 6; p++) {
                uint32_t bf[4];
                ldsm_x4(bf, bbase2 + p * 16 * HK_STRIDE * 2 + kk * 32);
                mma_bf16(c2[p][0], a, bf[0], bf[1]);
                mma_bf16(c2[p][1], a, bf[2], bf[3]);
            }
        }

        __syncthreads();   // all ldmatrix reads of this chunk's B-region done
        float* sdst = (float*)(smem + (ac ? SM_W1A : SM_XS));
#pragma unroll
        for (int p = 0; p < 6; p++) {
#pragma unroll
            for (int j = 0; j < 2; j++) {
                int col = p * 16 + j * 8 + 2 * (lane & 3);
                *(float2*)(sdst + r0 * SS_STRIDE + col) =
                    make_float2(c2[p][j][0], c2[p][j][1]);
                *(float2*)(sdst + (r0 + 8) * SS_STRIDE + col) =
                    make_float2(c2[p][j][2], c2[p][j][3]);
            }
        }
    }
    __syncthreads();

    // ---- fused softmax partials, 2-way t-split ILP (thread == a) ----------
    if (tid < AA) {
        int a = tid;
        const float* ssm = (a < 96) ? (const float*)(smem + SM_XS)
                                    : (const float*)(smem + SM_W1A);
        int acol = (a < 96) ? a : (a - 96);
        float qbv = ((const float*)(smem + AXH_QB))[a];
        int tmax = TT - t0; if (tmax > 128) tmax = 128;   // always >= 64

        // max pass over all 128 rows incl. padded (valid shift: exact cancel,
        // padded scores are tanh-bounded so no underflow risk). 2 indep chains.
        float M0 = -1e30f, M1 = -1e30f;
#pragma unroll 4
        for (int t = 0; t < 64; t++) {
            M0 = fmaxf(M0, ssm[t * SS_STRIDE + acol]);
            M1 = fmaxf(M1, ssm[(t + 64) * SS_STRIDE + acol]);
        }
        float M = fmaxf(M0, M1) + qbv;

        // sum pass: first 64 rows always valid; second half guarded.
        float Z0 = 0.f, S10 = 0.f, S20 = 0.f;
        float Z1 = 0.f, S11 = 0.f, S21 = 0.f;
        const float* vp = ht + ((size_t)b * TT + t0) * CC + n * DD + a;
#pragma unroll 2
        for (int t = 0; t < 64; t++) {
            float s = ssm[t * SS_STRIDE + acol] + qbv;
            float wv = __expf(s - M);
            float v = vp[(size_t)t * CC];
            Z0 += wv; S10 += wv * v; S20 += wv * v * v;
            int t2 = t + 64;
            if (t2 < tmax) {
                float s2 = ssm[t2 * SS_STRIDE + acol] + qbv;
                float wv2 = __expf(s2 - M);
                float v2 = vp[(size_t)t2 * CC];
                Z1 += wv2; S11 += wv2 * v2; S21 += wv2 * v2 * v2;
            }
        }
        g_pp[((size_t)bn * 16 + blockIdx.x) * AA + a] =
            make_float4(M, Z0 + Z1, S10 + S11, S20 + S21);
    }
}

// ---------------- K4: merge 16 tile partials -> output ---------------------
__global__ __launch_bounds__(192) void k_pool_merge(float* __restrict__ out) {
    int bn = blockIdx.x;
    int b = bn >> 3, n = bn & 7;
    int a = threadIdx.x;

    const float4* pp = g_pp + (size_t)bn * 16 * AA + a;
    float M = -1e30f;
#pragma unroll
    for (int s = 0; s < 16; s++) M = fmaxf(M, pp[s * AA].x);
    float Zt = 0.f, S1t = 0.f, S2t = 0.f;
#pragma unroll
    for (int s = 0; s < 16; s++) {
        float4 p = pp[s * AA];
        float c = __expf(p.x - M);
        Zt += p.y * c; S1t += p.z * c; S2t += p.w * c;
    }
    float mu = S1t / Zt;
    float ex2 = S2t / Zt;
    float rh = sqrtf(fmaxf(ex2 - mu * mu, 1e-9f));
    out[(size_t)b * (2 * CC) + n * DD + a] = mu;
    out[(size_t)b * (2 * CC) + CC + n * DD + a] = rh;
}

// ---------------- launcher ------------------------------------------------
extern "C" void kernel_launch(void* const* d_in, const int* in_sizes, int n_in,
                              void* d_out, int out_size) {
    const float* ht       = (const float*)d_in[0];
    const float* k_proj_W = (const float*)d_in[1];
    const float* query    = (const float*)d_in[2];
    const float* uk_W     = (const float*)d_in[3];
    const float* u_q1W    = (const float*)d_in[4];
    const float* u_q2     = (const float*)d_in[5];
    const float* vhq      = (const float*)d_in[6];
    const float* vhk      = (const float*)d_in[7];
    const float* vcq      = (const float*)d_in[8];
    const float* vck      = (const float*)d_in[9];
    const float* k_proj_b = (const float*)d_in[10];
    const float* q_b      = (const float*)d_in[11];
    const float* u_q1b    = (const float*)d_in[12];
    const float* bnc_g    = (const float*)d_in[13];
    const float* bnc_b    = (const float*)d_in[14];
    const float* bnc_m    = (const float*)d_in[15];
    const float* bnc_v    = (const float*)d_in[16];
    const float* bnk_g    = (const float*)d_in[17];
    const float* bnk_b    = (const float*)d_in[18];
    const float* bnk_m    = (const float*)d_in[19];
    const float* bnk_v    = (const float*)d_in[20];
    float* out = (float*)d_out;

    static int smem_set = 0;
    if (!smem_set) {
        cudaFuncSetAttribute(k_scores_mma,
                             cudaFuncAttributeMaxDynamicSharedMemorySize, SMEM_SC);
        smem_set = 1;
    }

    dim3 gs(CC / 128, BB);
    dim3 bs(128, 8);
    k_stats<<<gs, bs>>>(ht);

    dim3 gt(48, NH), bt(32, 8);
    k_prepw<<<gt, bt>>>(k_proj_W);
    k_prepq<<<gt, bt>>>(query);
    dim3 gq(8, NH);
    k_qdot<<<gq, 256>>>(query, vhq, vcq);

    dim3 ga(8, NH);
    k_ctx_a<<<ga, 256>>>(uk_W, u_q1W, u_q1b, bnc_g, bnc_b, bnc_m, bnc_v);
    dim3 gb(6, NH);
    k_ctx_b<<<gb, 256>>>(u_q2);
    k_ctx_c<<<BB * NH, 256>>>(vck);

    dim3 gsc(16, BB * NH);
    k_scores_mma<<<gsc, 256, SMEM_SC>>>(ht, k_proj_b, bnk_g, bnk_b, bnk_m, bnk_v,
                                        vhk, q_b);

    k_pool_merge<<<BB * NH, AA>>>(out);
}

// round 13
// speedup vs baseline: 1.2748x; 1.0011x over previous
#include <cuda_runtime.h>
#include <cuda_bf16.h>
#include <math.h>
#include <stdint.h>

// Problem constants
#define BB 16
#define TT 2000
#define CC 1536
#define NH 8
#define DD 192
#define QQ 256
#define AA 192

// ===================== warp-MMA helpers (sm_80+ baseline) ==================
__device__ __forceinline__ uint32_t smem_u32(const void* p) {
    uint32_t a;
    asm("{ .reg .u64 t; cvta.to.shared.u64 t, %1; cvt.u32.u64 %0, t; }"
        : "=r"(a) : "l"(p));
    return a;
}
__device__ __forceinline__ void ldsm_x4(uint32_t r[4], uint32_t addr) {
    asm volatile("ldmatrix.sync.aligned.m8n8.x4.shared.b16 {%0,%1,%2,%3}, [%4];"
                 : "=r"(r[0]), "=r"(r[1]), "=r"(r[2]), "=r"(r[3]) : "r"(addr));
}
__device__ __forceinline__ void mma_bf16(float c[4], const uint32_t a[4],
                                         uint32_t b0, uint32_t b1) {
    asm volatile("mma.sync.aligned.m16n8k16.row.col.f32.bf16.bf16.f32 "
                 "{%0,%1,%2,%3}, {%4,%5,%6,%7}, {%8,%9}, {%0,%1,%2,%3};"
                 : "+f"(c[0]), "+f"(c[1]), "+f"(c[2]), "+f"(c[3])
                 : "r"(a[0]), "r"(a[1]), "r"(a[2]), "r"(a[3]), "r"(b0), "r"(b1));
}
__device__ __forceinline__ uint32_t pack_bf(float lo, float hi) {
    uint32_t r;
    asm("cvt.rn.bf16x2.f32 %0, %1, %2;" : "=r"(r) : "f"(hi), "f"(lo));
    return r;
}
__device__ __forceinline__ float bflo(uint32_t u) { return __uint_as_float(u << 16); }
__device__ __forceinline__ float bfhi(uint32_t u) { return __uint_as_float(u & 0xffff0000u); }
__device__ __forceinline__ float tanha(float x) {
    float r; asm("tanh.approx.f32 %0, %1;" : "=f"(r) : "f"(x)); return r;
}
#define CP_ASYNC16(dst, src) \
    asm volatile("cp.async.cg.shared.global [%0], [%1], 16;" :: "r"(dst), "l"(src))
#define CP_COMMIT() asm volatile("cp.async.commit_group;" ::: "memory")
#define CP_WAIT0() asm volatile("cp.async.wait_group 0;" ::: "memory")
#define CP_WAIT1() asm volatile("cp.async.wait_group 1;" ::: "memory")

// ---------------- scratch (device globals: no allocations allowed) --------
__device__ float g_c[BB * CC * 2];
__device__ float g_hck[BB * NH * QQ];
__device__ float g_t1[BB * NH * QQ];
__device__ float g_cq2[BB * NH * AA];
__device__ float g_vcqsum[NH * AA];
__device__ float g_ckdot[BB * NH];
__device__ float g_qdotp[NH * 8];
__device__ float g_qT[NH * AA * QQ];                          // query^T [n][a][q]
__device__ __nv_bfloat16 g_w1t[NH * QQ * DD];                 // W1^T [n][q][d] bf16
__device__ __nv_bfloat16 g_hcqT[(size_t)BB * NH * AA * QQ];   // hcq^T/sqrt(Q) [bn][a][q]
__device__ float4 g_pp[BB * NH * 16 * AA];                    // pool partials per tile

// ---------------- K1: mean/std over time ----------------------------------
__global__ void k_stats(const float* __restrict__ ht) {
    int b = blockIdx.y;
    int ch = blockIdx.x * 128 + threadIdx.x;
    int ty = threadIdx.y;
    float s = 0.f, s2 = 0.f;
    const float* p = ht + (size_t)b * TT * CC + ch;
    for (int t = ty; t < TT; t += 8) {
        float v = p[(size_t)t * CC];
        s += v; s2 += v * v;
    }
    __shared__ float sh0[8][128];
    __shared__ float sh1[8][128];
    sh0[ty][threadIdx.x] = s;
    sh1[ty][threadIdx.x] = s2;
    __syncthreads();
    if (ty == 0) {
        for (int j = 1; j < 8; j++) { s += sh0[j][threadIdx.x]; s2 += sh1[j][threadIdx.x]; }
        float mean = s * (1.f / TT);
        float var = (s2 - (float)TT * mean * mean) * (1.f / (TT - 1));
        float sd = sqrtf(fmaxf(var, 0.f));
        g_c[((size_t)b * CC + ch) * 2 + 0] = mean;
        g_c[((size_t)b * CC + ch) * 2 + 1] = sd;
    }
}

// ---------------- K0: qdot partials + vcq_sum (coalesced via g_qT) ---------
__global__ void k_qdot(const float* __restrict__ query, const float* __restrict__ vhq,
                       const float* __restrict__ vcq) {
    int s = blockIdx.x;
    int n = blockIdx.y;
    int tid = threadIdx.x;
    (void)query;
    float acc = 0.f;
    int base = s * (AA * QQ / 8);
    const float* qt = g_qT + (size_t)n * AA * QQ;
    const float* vh = vhq + (size_t)n * AA * QQ;
    for (int ii = tid; ii < AA * QQ / 8; ii += 256) {
        int i = base + ii;                 // i = a*QQ + q; both operands contiguous
        acc += qt[i] * vh[i];
    }
    __shared__ float red[256];
    red[tid] = acc;
    __syncthreads();
    for (int off = 128; off > 0; off >>= 1) {
        if (tid < off) red[tid] += red[tid + off];
        __syncthreads();
    }
    if (tid == 0) g_qdotp[n * 8 + s] = red[0];

    int w = tid >> 5, lane = tid & 31;
    for (int r = w; r < AA / 8; r += 8) {
        int a = s * (AA / 8) + r;
        const float* vp = vcq + ((size_t)n * AA + a) * QQ;
        float sum = 0.f;
        for (int q = lane; q < QQ; q += 32) sum += vp[q];
#pragma unroll
        for (int o = 16; o > 0; o >>= 1) sum += __shfl_down_sync(0xffffffffu, sum, o);
        if (lane == 0) g_vcqsum[n * AA + a] = sum;
    }
}

// ---------------- prep: W1^T -> bf16 (tiled transpose) ---------------------
__global__ void k_prepw(const float* __restrict__ W1) {
    int n = blockIdx.y;
    int tile = blockIdx.x;
    int d0 = (tile % 6) * 32, q0 = (tile / 6) * 32;
    int tx = threadIdx.x, ty = threadIdx.y;
    __shared__ float tl[32][33];
#pragma unroll
    for (int j = 0; j < 4; j++)
        tl[ty + j * 8][tx] = W1[((size_t)n * DD + d0 + ty + j * 8) * QQ + q0 + tx];
    __syncthreads();
#pragma unroll
    for (int j = 0; j < 4; j++)
        g_w1t[((size_t)n * QQ + q0 + ty + j * 8) * DD + d0 + tx] =
            __float2bfloat16_rn(tl[tx][ty + j * 8]);
}

// ---------------- prep: query^T fp32 (tiled transpose) ---------------------
__global__ void k_prepq(const float* __restrict__ query) {
    int n = blockIdx.y;
    int tile = blockIdx.x;
    int a0 = (tile % 6) * 32, q0 = (tile / 6) * 32;
    int tx = threadIdx.x, ty = threadIdx.y;
    __shared__ float tl[32][33];
#pragma unroll
    for (int j = 0; j < 4; j++)
        tl[ty + j * 8][tx] = query[((size_t)n * QQ + q0 + ty + j * 8) * AA + a0 + tx];
    __syncthreads();
#pragma unroll
    for (int j = 0; j < 4; j++)
        g_qT[((size_t)n * AA + a0 + ty + j * 8) * QQ + q0 + tx] = tl[tx][ty + j * 8];
}

// ---------------- ctx-a: hck + t1 for all 16 b per block -------------------
__global__ __launch_bounds__(256) void k_ctx_a(
        const float* __restrict__ uk_W, const float* __restrict__ u_q1W,
        const float* __restrict__ u_q1b,
        const float* __restrict__ bnc_g, const float* __restrict__ bnc_b,
        const float* __restrict__ bnc_m, const float* __restrict__ bnc_v) {
    int n = blockIdx.y, qt = blockIdx.x;
    int tid = threadIdx.x;
    int qi = tid & 31, sl = tid >> 5;
    int q = qt * 32 + qi;

    __shared__ float c_sh[16 * 384];
    __shared__ float part[8 * 16 * 33];

    for (int i = tid; i < 16 * 384; i += 256) {
        int b = i / 384, l = i - b * 384;
        c_sh[i] = g_c[((size_t)b * CC + n * DD) * 2 + l];
    }
    __syncthreads();

    float ak[16], aq[16];
#pragma unroll
    for (int b = 0; b < 16; b++) { ak[b] = 0.f; aq[b] = 0.f; }
    {
        const float* uk = uk_W + ((size_t)n * 384) * QQ + q;
        const float* u1 = u_q1W + ((size_t)n * 384) * QQ + q;
        int l0 = sl * 48;
        for (int l = l0; l < l0 + 48; l++) {
            float wk = uk[(size_t)l * QQ];
            float w1 = u1[(size_t)l * QQ];
            const float* cb = c_sh + l;
#pragma unroll
            for (int b = 0; b < 16; b++) {
                float cv = cb[b * 384];
                ak[b] = fmaf(cv, wk, ak[b]);
                aq[b] = fmaf(cv, w1, aq[b]);
            }
        }
    }

#pragma unroll
    for (int b = 0; b < 16; b++) part[(sl * 16 + b) * 33 + qi] = ak[b];
    __syncthreads();
    {
        int bp = tid >> 5;
        float s0 = 0.f, s1 = 0.f;
#pragma unroll
        for (int s = 0; s < 8; s++) {
            s0 += part[(s * 16 + bp) * 33 + qi];
            s1 += part[(s * 16 + bp + 8) * 33 + qi];
        }
        g_hck[((size_t)(bp * NH + n)) * QQ + q] = s0;
        g_hck[((size_t)((bp + 8) * NH + n)) * QQ + q] = s1;
    }
    __syncthreads();

#pragma unroll
    for (int b = 0; b < 16; b++) part[(sl * 16 + b) * 33 + qi] = aq[b];
    __syncthreads();
    {
        int bp = tid >> 5;
        float s0 = 0.f, s1 = 0.f;
#pragma unroll
        for (int s = 0; s < 8; s++) {
            s0 += part[(s * 16 + bp) * 33 + qi];
            s1 += part[(s * 16 + bp + 8) * 33 + qi];
        }
        float bias = u_q1b[n * QQ + q];
        float grs = bnc_g[q] * rsqrtf(bnc_v[q] + 1e-5f);
        float beta = bnc_b[q] - grs * bnc_m[q];
        float r0 = fmaxf(s0 + bias, 0.f);
        float r1 = fmaxf(s1 + bias, 0.f);
        g_t1[((size_t)(bp * NH + n)) * QQ + q] = tanhf(fmaf(grs, r0, beta));
        g_t1[((size_t)((bp + 8) * NH + n)) * QQ + q] = tanhf(fmaf(grs, r1, beta));
    }
}

// ---------------- ctx-b: cq2 = t1 @ u_q2 for all 16 b per block ------------
__global__ __launch_bounds__(256) void k_ctx_b(const float* __restrict__ u_q2) {
    int n = blockIdx.y, at = blockIdx.x;
    int tid = threadIdx.x;
    int ai = tid & 31, msl = tid >> 5;
    int a = at * 32 + ai;

    __shared__ float t1_sh[16 * 256];
    __shared__ float part[8 * 16 * 33];

    for (int i = tid; i < 16 * 256; i += 256) {
        int b = i >> 8, m = i & 255;
        t1_sh[i] = g_t1[((size_t)(b * NH + n)) * QQ + m];
    }
    __syncthreads();

    float acc[16];
#pragma unroll
    for (int b = 0; b < 16; b++) acc[b] = 0.f;
    {
        const float* u2 = u_q2 + (size_t)n * QQ * AA + a;
        int m0 = msl * 32;
        for (int m = m0; m < m0 + 32; m++) {
            float w = u2[(size_t)m * AA];
            const float* tb = t1_sh + m;
#pragma unroll
            for (int b = 0; b < 16; b++)
                acc[b] = fmaf(tb[b * 256], w, acc[b]);
        }
    }
#pragma unroll
    for (int b = 0; b < 16; b++) part[(msl * 16 + b) * 33 + ai] = acc[b];
    __syncthreads();
    {
        int bp = tid >> 5;
        float s0 = 0.f, s1 = 0.f;
#pragma unroll
        for (int s = 0; s < 8; s++) {
            s0 += part[(s * 16 + bp) * 33 + ai];
            s1 += part[(s * 16 + bp + 8) * 33 + ai];
        }
        g_cq2[((size_t)(bp * NH + n)) * AA + a] = s0;
        g_cq2[((size_t)((bp + 8) * NH + n)) * AA + a] = s1;
    }
}

// ---------------- ctx-c: scalars + hcqT write (coalesced) ------------------
__global__ __launch_bounds__(256) void k_ctx_c(const float* __restrict__ vck) {
    int bn = blockIdx.x;
    int n = bn & 7;
    int tid = threadIdx.x;

    __shared__ float cq2_sh[AA];
    __shared__ float red[256];
    __shared__ float lamq_sh;

    if (tid < AA) cq2_sh[tid] = g_cq2[(size_t)bn * AA + tid];

    red[tid] = g_hck[(size_t)bn * QQ + tid] * vck[n * QQ + tid];
    __syncthreads();
    for (int off = 128; off > 0; off >>= 1) {
        if (tid < off) red[tid] += red[tid + off];
        __syncthreads();
    }
    if (tid == 0) g_ckdot[bn] = red[0];
    __syncthreads();

    red[tid] = (tid < AA) ? cq2_sh[tid] * g_vcqsum[n * AA + tid] : 0.f;
    __syncthreads();
    for (int off = 128; off > 0; off >>= 1) {
        if (tid < off) red[tid] += red[tid + off];
        __syncthreads();
    }
    if (tid == 0) {
        float qd = 0.f;
#pragma unroll
        for (int k = 0; k < 8; k++) qd += g_qdotp[n * 8 + k];
        lamq_sh = 1.f / (1.f + __expf(-(qd + red[0])));
    }
    __syncthreads();

    float lq = lamq_sh;
    const float inv_sq = 1.f / 16.f;
    const float* qtp = g_qT + (size_t)n * AA * QQ + tid;
    __nv_bfloat16* op = g_hcqT + (size_t)bn * AA * QQ + tid;
#pragma unroll 4
    for (int a = 0; a < AA; a++) {
        float qv = qtp[(size_t)a * QQ];
        float v = (fmaf(lq, cq2_sh[a] - qv, qv)) * inv_sq;
        op[(size_t)a * QQ] = __float2bfloat16_rn(v);
    }
}

// ---------------- K3: fused scores + softmax-partial kernel ----------------
#define XS_STRIDE 200
#define HK_STRIDE 264
#define SS_STRIDE 100
#define SM_XS 0
#define SM_HK 51200
#define SM_W1A 118784
#define SM_W1B 144384
#define SM_AUX 169984
#define AXH_HCK  (SM_AUX + 0)
#define AXH_KBV  (SM_AUX + 1024)
#define AXH_GRS  (SM_AUX + 2048)
#define AXH_BETA (SM_AUX + 3072)
#define AXH_VHK  (SM_AUX + 4096)
#define AXH_QB   (SM_AUX + 5120)
#define AXH_LAM  (SM_AUX + 6144)
#define SMEM_SC  (SM_AUX + 6656)

__global__ __launch_bounds__(256) void k_scores_mma(
        const float* __restrict__ ht, const float* __restrict__ kb,
        const float* __restrict__ bg, const float* __restrict__ bbias,
        const float* __restrict__ bm, const float* __restrict__ bv,
        const float* __restrict__ vhk, const float* __restrict__ qb) {
    extern __shared__ char smem[];
    uint32_t sb = smem_u32(smem);
    int tid = threadIdx.x;
    int w = tid >> 5, lane = tid & 31;
    int bn = blockIdx.y;
    int b = bn >> 3, n = bn & 7;
    int t0 = blockIdx.x * 128;

    // kick off W1 chunk 0 async load immediately
    {
        const uint4* wsrc = (const uint4*)(g_w1t + (size_t)n * QQ * DD);
#pragma unroll
        for (int it = 0; it < 6; it++) {
            int idx = it * 256 + tid;
            int row = idx / 24, c8 = idx - row * 24;
            CP_ASYNC16(sb + SM_W1A + (row * XS_STRIDE + c8 * 8) * 2, wsrc + idx);
        }
        CP_COMMIT();
    }

    // aux constant arrays
    {
        int i = tid;
        float g = bg[i];
        float grs = g * rsqrtf(bv[i] + 1e-5f);
        ((float*)(smem + AXH_GRS))[i] = grs;
        ((float*)(smem + AXH_BETA))[i] = bbias[i] - grs * bm[i];
        ((float*)(smem + AXH_HCK))[i] = g_hck[(size_t)bn * QQ + i];
        ((float*)(smem + AXH_KBV))[i] = kb[n * QQ + i];
        ((float*)(smem + AXH_VHK))[i] = vhk[n * QQ + i];
        if (i < AA) ((float*)(smem + AXH_QB))[i] = qb[n * AA + i];
    }

    // ---- load x tile (fp32 -> bf16), rows padded with zeros past TT ----
    {
        const float* xb = ht + ((size_t)b * TT + t0) * CC + n * DD;
        for (int it = 0; it < 24; it++) {
            int idx = it * 256 + tid;
            int row = idx / 48, c4 = idx - row * 48;
            float4 v = make_float4(0.f, 0.f, 0.f, 0.f);
            if (t0 + row < TT) v = *(const float4*)(xb + (size_t)row * CC + c4 * 4);
            uint2 pk = make_uint2(pack_bf(v.x, v.y), pack_bf(v.z, v.w));
            *(uint2*)(smem + SM_XS + (row * XS_STRIDE + c4 * 4) * 2) = pk;
        }
    }

    uint32_t abase = sb + SM_XS + ((w * 16 + (lane & 15)) * XS_STRIDE + (lane >> 4) * 8) * 2;
    uint32_t boff_w1 = (((lane >> 4) * 8 + (lane & 7)) * XS_STRIDE + ((lane >> 3) & 1) * 8) * 2;

    // ---- GEMM1 over 4 q-chunks of 64, double-buffered W1; lambda in regs --
    float lam0 = 0.f, lam1 = 0.f;
    for (int qc = 0; qc < 4; qc++) {
        if (qc < 3) {
            int buf = ((qc + 1) & 1) ? SM_W1B : SM_W1A;
            const uint4* wsrc = (const uint4*)(g_w1t + ((size_t)n * QQ + (qc + 1) * 64) * DD);
#pragma unroll
            for (int it = 0; it < 6; it++) {
                int idx = it * 256 + tid;
                int row = idx / 24, c8 = idx - row * 24;
                CP_ASYNC16(sb + buf + (row * XS_STRIDE + c8 * 8) * 2, wsrc + idx);
            }
            CP_COMMIT();
            CP_WAIT1();
        } else {
            CP_WAIT0();
        }
        __syncthreads();

        uint32_t bbase = sb + ((qc & 1) ? SM_W1B : SM_W1A) + boff_w1;

        float c[4][2][4];
#pragma unroll
        for (int p = 0; p < 4; p++)
#pragma unroll
            for (int j = 0; j < 2; j++)
#pragma unroll
                for (int e = 0; e < 4; e++) c[p][j][e] = 0.f;

        for (int kk = 0; kk < 12; kk++) {
            uint32_t a[4];
            ldsm_x4(a, abase + kk * 32);
#pragma unroll
            for (int p = 0; p < 4; p++) {
                uint32_t bf[4];
                ldsm_x4(bf, bbase + p * 16 * XS_STRIDE * 2 + kk * 32);
                mma_bf16(c[p][0], a, bf[0], bf[1]);
                mma_bf16(c[p][1], a, bf[2], bf[3]);
            }
        }

        const float* vhk_s = (const float*)(smem + AXH_VHK);
        int r0 = w * 16 + (lane >> 2);
#pragma unroll
        for (int p = 0; p < 4; p++) {
#pragma unroll
            for (int j = 0; j < 2; j++) {
                int col = qc * 64 + p * 16 + j * 8 + 2 * (lane & 3);
                float v0 = vhk_s[col], v1 = vhk_s[col + 1];
                lam0 += c[p][j][0] * v0 + c[p][j][1] * v1;
                lam1 += c[p][j][2] * v0 + c[p][j][3] * v1;
                *(uint32_t*)(smem + SM_HK + (r0 * HK_STRIDE + col) * 2) =
                    pack_bf(c[p][j][0], c[p][j][1]);
                *(uint32_t*)(smem + SM_HK + ((r0 + 8) * HK_STRIDE + col) * 2) =
                    pack_bf(c[p][j][2], c[p][j][3]);
            }
        }
        __syncthreads();
    }

    // prefetch hcq chunk 0 into XS region (xs dead after GEMM1)
    {
        const uint4* hs = (const uint4*)(g_hcqT + (size_t)bn * AA * QQ);
#pragma unroll
        for (int it = 0; it < 12; it++) {
            int idx = it * 256 + tid;
            int row = idx / 32, c8 = idx - row * 32;
            CP_ASYNC16(sb + SM_XS + (row * HK_STRIDE + c8 * 8) * 2, hs + idx);
        }
        CP_COMMIT();
    }

    // lambda finalize
    lam0 += __shfl_xor_sync(0xffffffffu, lam0, 1);
    lam0 += __shfl_xor_sync(0xffffffffu, lam0, 2);
    lam1 += __shfl_xor_sync(0xffffffffu, lam1, 1);
    lam1 += __shfl_xor_sync(0xffffffffu, lam1, 2);
    {
        float ckd = g_ckdot[bn];
        if ((lane & 3) == 0) {
            float* lam_sh = (float*)(smem + AXH_LAM);
            lam_sh[w * 16 + (lane >> 2)] = 1.f / (1.f + __expf(-(lam0 + ckd)));
            lam_sh[w * 16 + (lane >> 2) + 8] = 1.f / (1.f + __expf(-(lam1 + ckd)));
        }
    }
    __syncthreads();

    // ---- activation in place (overlaps hcq chunk0 cp.async) ----
    {
        int row = w * 16 + (lane >> 1);
        int cb = (lane & 1) * 128;
        float lam = ((const float*)(smem + AXH_LAM))[row];
        const float* hck_s = (const float*)(smem + AXH_HCK);
        const float* kbv_s = (const float*)(smem + AXH_KBV);
        const float* grs_s = (const float*)(smem + AXH_GRS);
        const float* bet_s = (const float*)(smem + AXH_BETA);
        uint32_t* hp = (uint32_t*)(smem + SM_HK + (row * HK_STRIDE + cb) * 2);
        for (int j = 0; j < 16; j++) {
            uint4 v = *(uint4*)(hp + j * 4);
            uint32_t* vr = (uint32_t*)&v;
#pragma unroll
            for (int e = 0; e < 4; e++) {
                int c0 = cb + j * 8 + 2 * e;
                float h0 = bflo(vr[e]), h1 = bfhi(vr[e]);
                float m0 = fmaf(lam, hck_s[c0] - h0, h0) + kbv_s[c0];
                float m1 = fmaf(lam, hck_s[c0 + 1] - h1, h1) + kbv_s[c0 + 1];
                m0 = fmaxf(m0, 0.f); m1 = fmaxf(m1, 0.f);
                float a0 = tanha(fmaf(grs_s[c0], m0, bet_s[c0]));
                float a1 = tanha(fmaf(grs_s[c0 + 1], m1, bet_s[c0 + 1]));
                vr[e] = pack_bf(a0, a1);
            }
            *(uint4*)(hp + j * 4) = v;
        }
    }

    // ---- GEMM2 over 2 a-chunks of 96; fragments -> fp32 smem --------------
    uint32_t abase2 = sb + SM_HK + ((w * 16 + (lane & 15)) * HK_STRIDE + (lane >> 4) * 8) * 2;
    uint32_t boff_hcq = (((lane >> 4) * 8 + (lane & 7)) * HK_STRIDE + ((lane >> 3) & 1) * 8) * 2;
    int r0 = w * 16 + (lane >> 2);

    for (int ac = 0; ac < 2; ac++) {
        if (ac == 0) {
            const uint4* hs = (const uint4*)(g_hcqT + ((size_t)bn * AA + 96) * QQ);
#pragma unroll
            for (int it = 0; it < 12; it++) {
                int idx = it * 256 + tid;
                int row = idx / 32, c8 = idx - row * 32;
                CP_ASYNC16(sb + SM_W1A + (row * HK_STRIDE + c8 * 8) * 2, hs + idx);
            }
            CP_COMMIT();
            CP_WAIT1();
        } else {
            CP_WAIT0();
        }
        __syncthreads();

        uint32_t bbase2 = sb + (ac ? SM_W1A : SM_XS) + boff_hcq;

        float c2[6][2][4];
#pragma unroll
        for (int p = 0; p < 6; p++)
#pragma unroll
            for (int j = 0; j < 2; j++)
#pragma unroll
                for (int e = 0; e < 4; e++) c2[p][j][e] = 0.f;

        for (int kk = 0; kk < 16; kk++) {
            uint32_t a[4];
            ldsm_x4(a, abase2 + kk * 32);
#pragma unroll
            for (int p = 0; p < 6; p++) {
                uint32_t bf[4];
                ldsm_x4(bf, bbase2 + p * 16 * HK_STRIDE * 2 + kk * 32);
                mma_bf16(c2[p][0], a, bf[0], bf[1]);
                mma_bf16(c2[p][1], a, bf[2], bf[3]);
            }
        }

        __syncthreads();   // all ldmatrix reads of this chunk's B-region done
        float* sdst = (float*)(smem + (ac ? SM_W1A : SM_XS));
#pragma unroll
        for (int p = 0; p < 6; p++) {
#pragma unroll
            for (int j = 0; j < 2; j++) {
                int col = p * 16 + j * 8 + 2 * (lane & 3);
                *(float2*)(sdst + r0 * SS_STRIDE + col) =
                    make_float2(c2[p][j][0], c2[p][j][1]);
                *(float2*)(sdst + (r0 + 8) * SS_STRIDE + col) =
                    make_float2(c2[p][j][2], c2[p][j][3]);
            }
        }
    }
    __syncthreads();

    // ---- fused softmax partials, 2-way t-split ILP (thread == a) ----------
    if (tid < AA) {
        int a = tid;
        const float* ssm = (a < 96) ? (const float*)(smem + SM_XS)
                                    : (const float*)(smem + SM_W1A);
        int acol = (a < 96) ? a : (a - 96);
        float qbv = ((const float*)(smem + AXH_QB))[a];
        int tmax = TT - t0; if (tmax > 128) tmax = 128;   // always >= 64

        // max pass over all 128 rows incl. padded (valid shift: exact cancel,
        // padded scores are tanh-bounded so no underflow risk). 2 indep chains.
        float M0 = -1e30f, M1 = -1e30f;
#pragma unroll 4
        for (int t = 0; t < 64; t++) {
            M0 = fmaxf(M0, ssm[t * SS_STRIDE + acol]);
            M1 = fmaxf(M1, ssm[(t + 64) * SS_STRIDE + acol]);
        }
        float M = fmaxf(M0, M1) + qbv;

        // sum pass: first 64 rows always valid; second half guarded.
        float Z0 = 0.f, S10 = 0.f, S20 = 0.f;
        float Z1 = 0.f, S11 = 0.f, S21 = 0.f;
        const float* vp = ht + ((size_t)b * TT + t0) * CC + n * DD + a;
#pragma unroll 2
        for (int t = 0; t < 64; t++) {
            float s = ssm[t * SS_STRIDE + acol] + qbv;
            float wv = __expf(s - M);
            float v = vp[(size_t)t * CC];
            Z0 += wv; S10 += wv * v; S20 += wv * v * v;
            int t2 = t + 64;
            if (t2 < tmax) {
                float s2 = ssm[t2 * SS_STRIDE + acol] + qbv;
                float wv2 = __expf(s2 - M);
                float v2 = vp[(size_t)t2 * CC];
                Z1 += wv2; S11 += wv2 * v2; S21 += wv2 * v2 * v2;
            }
        }
        g_pp[((size_t)bn * 16 + blockIdx.x) * AA + a] =
            make_float4(M, Z0 + Z1, S10 + S11, S20 + S21);
    }
}

// ---------------- K4: merge 16 tile partials -> output ---------------------
__global__ __launch_bounds__(192) void k_pool_merge(float* __restrict__ out) {
    int bn = blockIdx.x;
    int b = bn >> 3, n = bn & 7;
    int a = threadIdx.x;

    const float4* pp = g_pp + (size_t)bn * 16 * AA + a;
    float M = -1e30f;
#pragma unroll
    for (int s = 0; s < 16; s++) M = fmaxf(M, pp[s * AA].x);
    float Zt = 0.f, S1t = 0.f, S2t = 0.f;
#pragma unroll
    for (int s = 0; s < 16; s++) {
        float4 p = pp[s * AA];
        float c = __expf(p.x - M);
        Zt += p.y * c; S1t += p.z * c; S2t += p.w * c;
    }
    float mu = S1t / Zt;
    float ex2 = S2t / Zt;
    float rh = sqrtf(fmaxf(ex2 - mu * mu, 1e-9f));
    out[(size_t)b * (2 * CC) + n * DD + a] = mu;
    out[(size_t)b * (2 * CC) + CC + n * DD + a] = rh;
}

// ---------------- launcher ------------------------------------------------
extern "C" void kernel_launch(void* const* d_in, const int* in_sizes, int n_in,
                              void* d_out, int out_size) {
    const float* ht       = (const float*)d_in[0];
    const float* k_proj_W = (const float*)d_in[1];
    const float* query    = (const float*)d_in[2];
    const float* uk_W     = (const float*)d_in[3];
    const float* u_q1W    = (const float*)d_in[4];
    const float* u_q2     = (const float*)d_in[5];
    const float* vhq      = (const float*)d_in[6];
    const float* vhk      = (const float*)d_in[7];
    const float* vcq      = (const float*)d_in[8];
    const float* vck      = (const float*)d_in[9];
    const float* k_proj_b = (const float*)d_in[10];
    const float* q_b      = (const float*)d_in[11];
    const float* u_q1b    = (const float*)d_in[12];
    const float* bnc_g    = (const float*)d_in[13];
    const float* bnc_b    = (const float*)d_in[14];
    const float* bnc_m    = (const float*)d_in[15];
    const float* bnc_v    = (const float*)d_in[16];
    const float* bnk_g    = (const float*)d_in[17];
    const float* bnk_b    = (const float*)d_in[18];
    const float* bnk_m    = (const float*)d_in[19];
    const float* bnk_v    = (const float*)d_in[20];
    float* out = (float*)d_out;

    static int smem_set = 0;
    if (!smem_set) {
        cudaFuncSetAttribute(k_scores_mma,
                             cudaFuncAttributeMaxDynamicSharedMemorySize, SMEM_SC);
        smem_set = 1;
    }

    dim3 gs(CC / 128, BB);
    dim3 bs(128, 8);
    k_stats<<<gs, bs>>>(ht);

    dim3 gt(48, NH), bt(32, 8);
    k_prepw<<<gt, bt>>>(k_proj_W);
    k_prepq<<<gt, bt>>>(query);
    dim3 gq(8, NH);
    k_qdot<<<gq, 256>>>(query, vhq, vcq);

    dim3 ga(8, NH);
    k_ctx_a<<<ga, 256>>>(uk_W, u_q1W, u_q1b, bnc_g, bnc_b, bnc_m, bnc_v);
    dim3 gb(6, NH);
    k_ctx_b<<<gb, 256>>>(u_q2);
    k_ctx_c<<<BB * NH, 256>>>(vck);

    dim3 gsc(16, BB * NH);
    k_scores_mma<<<gsc, 256, SMEM_SC>>>(ht, k_proj_b, bnk_g, bnk_b, bnk_m, bnk_v,
                                        vhk, q_b);

    k_pool_merge<<<BB * NH, AA>>>(out);
}

// round 14
// speedup vs baseline: 1.4429x; 1.1319x over previous
#include <cuda_runtime.h>
#include <cuda_bf16.h>
#include <math.h>
#include <stdint.h>

// Problem constants
#define BB 16
#define TT 2000
#define CC 1536
#define NH 8
#define DD 192
#define QQ 256
#define AA 192

// ===================== warp-MMA helpers (sm_80+ baseline) ==================
__device__ __forceinline__ uint32_t smem_u32(const void* p) {
    uint32_t a;
    asm("{ .reg .u64 t; cvta.to.shared.u64 t, %1; cvt.u32.u64 %0, t; }"
        : "=r"(a) : "l"(p));
    return a;
}
__device__ __forceinline__ void ldsm_x4(uint32_t r[4], uint32_t addr) {
    asm volatile("ldmatrix.sync.aligned.m8n8.x4.shared.b16 {%0,%1,%2,%3}, [%4];"
                 : "=r"(r[0]), "=r"(r[1]), "=r"(r[2]), "=r"(r[3]) : "r"(addr));
}
__device__ __forceinline__ void mma_bf16(float c[4], const uint32_t a[4],
                                         uint32_t b0, uint32_t b1) {
    asm volatile("mma.sync.aligned.m16n8k16.row.col.f32.bf16.bf16.f32 "
                 "{%0,%1,%2,%3}, {%4,%5,%6,%7}, {%8,%9}, {%0,%1,%2,%3};"
                 : "+f"(c[0]), "+f"(c[1]), "+f"(c[2]), "+f"(c[3])
                 : "r"(a[0]), "r"(a[1]), "r"(a[2]), "r"(a[3]), "r"(b0), "r"(b1));
}
__device__ __forceinline__ uint32_t pack_bf(float lo, float hi) {
    uint32_t r;
    asm("cvt.rn.bf16x2.f32 %0, %1, %2;" : "=r"(r) : "f"(hi), "f"(lo));
    return r;
}
__device__ __forceinline__ float bflo(uint32_t u) { return __uint_as_float(u << 16); }
__device__ __forceinline__ float bfhi(uint32_t u) { return __uint_as_float(u & 0xffff0000u); }
__device__ __forceinline__ float tanha(float x) {
    float r; asm("tanh.approx.f32 %0, %1;" : "=f"(r) : "f"(x)); return r;
}
#define CP_ASYNC16(dst, src) \
    asm volatile("cp.async.cg.shared.global [%0], [%1], 16;" :: "r"(dst), "l"(src))
#define CP_COMMIT() asm volatile("cp.async.commit_group;" ::: "memory")
#define CP_WAIT0() asm volatile("cp.async.wait_group 0;" ::: "memory")
#define CP_WAIT1() asm volatile("cp.async.wait_group 1;" ::: "memory")

// ---------------- scratch (device globals: no allocations allowed) --------
__device__ float g_c[BB * CC * 2];
__device__ float g_hck[BB * NH * QQ];
__device__ float g_t1[BB * NH * QQ];
__device__ float g_cq2[BB * NH * AA];
__device__ float g_vcqsum[NH * AA];
__device__ float g_ckdotp[BB * NH * 8];     // ckdot partials per qtile
__device__ float g_vcqdotp[BB * NH * 6];    // vcqdot partials per atile
__device__ float g_qdotp[NH * 8];
__device__ __nv_bfloat16 g_w1t[NH * QQ * DD];               // W1^T [n][q][d] bf16
__device__ __nv_bfloat16 g_qTb[NH * AA * QQ];               // query^T/sqrt(Q) [n][a][q] bf16
__device__ float4 g_pp[BB * NH * 16 * AA];                  // pool partials per tile

// ---------------- K-front: stats + prepw + prepq + qdot (one launch) -------
__global__ __launch_bounds__(256) void k_front(
        const float* __restrict__ ht, const float* __restrict__ W1,
        const float* __restrict__ query, const float* __restrict__ vhq,
        const float* __restrict__ vcq) {
    __shared__ float shbuf[1088];
    int bid = blockIdx.x;
    int tid = threadIdx.x;

    if (bid < 384) {
        // ---- stats: 24 ch-tiles x 16 b; 64 channels, 4 t-slices ----
        int b = bid / 24, cht = bid % 24;
        int c = tid & 63, sl = tid >> 6;
        int ch = cht * 64 + c;
        float s = 0.f, s2 = 0.f;
        const float* p = ht + (size_t)b * TT * CC + ch;
        for (int t = sl; t < TT; t += 4) {
            float v = p[(size_t)t * CC];
            s += v; s2 += v * v;
        }
        shbuf[sl * 64 + c] = s;
        shbuf[256 + sl * 64 + c] = s2;
        __syncthreads();
        if (sl == 0) {
            for (int j = 1; j < 4; j++) { s += shbuf[j * 64 + c]; s2 += shbuf[256 + j * 64 + c]; }
            float mean = s * (1.f / TT);
            float var = (s2 - (float)TT * mean * mean) * (1.f / (TT - 1));
            float sd = sqrtf(fmaxf(var, 0.f));
            g_c[((size_t)b * CC + ch) * 2 + 0] = mean;
            g_c[((size_t)b * CC + ch) * 2 + 1] = sd;
        }
    } else if (bid < 768) {
        // ---- prepw: W1^T -> bf16, 48 tiles x 8 n ----
        int idx = bid - 384;
        int tile = idx % 48, n = idx / 48;
        int d0 = (tile % 6) * 32, q0 = (tile / 6) * 32;
        int tx = tid & 31, ty = tid >> 5;
#pragma unroll
        for (int j = 0; j < 4; j++)
            shbuf[(ty + j * 8) * 33 + tx] = W1[((size_t)n * DD + d0 + ty + j * 8) * QQ + q0 + tx];
        __syncthreads();
#pragma unroll
        for (int j = 0; j < 4; j++)
            g_w1t[((size_t)n * QQ + q0 + ty + j * 8) * DD + d0 + tx] =
                __float2bfloat16_rn(shbuf[tx * 33 + ty + j * 8]);
    } else if (bid < 1152) {
        // ---- prepq: query^T / sqrt(Q) -> bf16, 48 tiles x 8 n ----
        int idx = bid - 768;
        int tile = idx % 48, n = idx / 48;
        int a0 = (tile % 6) * 32, q0 = (tile / 6) * 32;
        int tx = tid & 31, ty = tid >> 5;
#pragma unroll
        for (int j = 0; j < 4; j++)
            shbuf[(ty + j * 8) * 33 + tx] = query[((size_t)n * QQ + q0 + ty + j * 8) * AA + a0 + tx];
        __syncthreads();
#pragma unroll
        for (int j = 0; j < 4; j++)
            g_qTb[((size_t)n * AA + a0 + ty + j * 8) * QQ + q0 + tx] =
                __float2bfloat16_rn(shbuf[tx * 33 + ty + j * 8] * (1.f / 16.f));
    } else {
        // ---- qdot partials + vcq_sum: 8 slices x 8 n ----
        int idx = bid - 1152;
        int s = idx % 8, n = idx / 8;
        float acc = 0.f;
        int base = s * (AA * QQ / 8);
        for (int ii = tid; ii < AA * QQ / 8; ii += 256) {
            int i = base + ii;
            int a = i >> 8, q = i & 255;
            acc += query[(n * QQ + q) * AA + a] * vhq[n * AA * QQ + i];
        }
        shbuf[tid] = acc;
        __syncthreads();
        for (int off = 128; off > 0; off >>= 1) {
            if (tid < off) shbuf[tid] += shbuf[tid + off];
            __syncthreads();
        }
        if (tid == 0) g_qdotp[n * 8 + s] = shbuf[0];

        int w = tid >> 5, lane = tid & 31;
        for (int r = w; r < AA / 8; r += 8) {
            int a = s * (AA / 8) + r;
            const float* vp = vcq + ((size_t)n * AA + a) * QQ;
            float sum = 0.f;
            for (int q = lane; q < QQ; q += 32) sum += vp[q];
#pragma unroll
            for (int o = 16; o > 0; o >>= 1) sum += __shfl_down_sync(0xffffffffu, sum, o);
            if (lane == 0) g_vcqsum[n * AA + a] = sum;
        }
    }
}

// ---------------- ctx-a: hck + t1 + ckdot partials -------------------------
__global__ __launch_bounds__(256) void k_ctx_a(
        const float* __restrict__ uk_W, const float* __restrict__ u_q1W,
        const float* __restrict__ u_q1b, const float* __restrict__ vck,
        const float* __restrict__ bnc_g, const float* __restrict__ bnc_b,
        const float* __restrict__ bnc_m, const float* __restrict__ bnc_v) {
    int n = blockIdx.y, qt = blockIdx.x;
    int tid = threadIdx.x;
    int qi = tid & 31, sl = tid >> 5;
    int q = qt * 32 + qi;

    __shared__ float c_sh[16 * 384];
    __shared__ float part[8 * 16 * 33];

    for (int i = tid; i < 16 * 384; i += 256) {
        int b = i / 384, l = i - b * 384;
        c_sh[i] = g_c[((size_t)b * CC + n * DD) * 2 + l];
    }
    __syncthreads();

    float ak[16], aq[16];
#pragma unroll
    for (int b = 0; b < 16; b++) { ak[b] = 0.f; aq[b] = 0.f; }
    {
        const float* uk = uk_W + ((size_t)n * 384) * QQ + q;
        const float* u1 = u_q1W + ((size_t)n * 384) * QQ + q;
        int l0 = sl * 48;
        for (int l = l0; l < l0 + 48; l++) {
            float wk = uk[(size_t)l * QQ];
            float w1 = u1[(size_t)l * QQ];
            const float* cb = c_sh + l;
#pragma unroll
            for (int b = 0; b < 16; b++) {
                float cv = cb[b * 384];
                ak[b] = fmaf(cv, wk, ak[b]);
                aq[b] = fmaf(cv, w1, aq[b]);
            }
        }
    }

#pragma unroll
    for (int b = 0; b < 16; b++) part[(sl * 16 + b) * 33 + qi] = ak[b];
    __syncthreads();
    {
        int bp = tid >> 5;
        float s0 = 0.f, s1 = 0.f;
#pragma unroll
        for (int s = 0; s < 8; s++) {
            s0 += part[(s * 16 + bp) * 33 + qi];
            s1 += part[(s * 16 + bp + 8) * 33 + qi];
        }
        g_hck[((size_t)(bp * NH + n)) * QQ + q] = s0;
        g_hck[((size_t)((bp + 8) * NH + n)) * QQ + q] = s1;

        // ckdot partials for this qtile
        float vckq = vck[n * QQ + q];
        float p0 = s0 * vckq, p1 = s1 * vckq;
#pragma unroll
        for (int o = 16; o > 0; o >>= 1) {
            p0 += __shfl_down_sync(0xffffffffu, p0, o);
            p1 += __shfl_down_sync(0xffffffffu, p1, o);
        }
        if (qi == 0) {
            g_ckdotp[(bp * NH + n) * 8 + qt] = p0;
            g_ckdotp[((bp + 8) * NH + n) * 8 + qt] = p1;
        }
    }
    __syncthreads();

#pragma unroll
    for (int b = 0; b < 16; b++) part[(sl * 16 + b) * 33 + qi] = aq[b];
    __syncthreads();
    {
        int bp = tid >> 5;
        float s0 = 0.f, s1 = 0.f;
#pragma unroll
        for (int s = 0; s < 8; s++) {
            s0 += part[(s * 16 + bp) * 33 + qi];
            s1 += part[(s * 16 + bp + 8) * 33 + qi];
        }
        float bias = u_q1b[n * QQ + q];
        float grs = bnc_g[q] * rsqrtf(bnc_v[q] + 1e-5f);
        float beta = bnc_b[q] - grs * bnc_m[q];
        float r0 = fmaxf(s0 + bias, 0.f);
        float r1 = fmaxf(s1 + bias, 0.f);
        g_t1[((size_t)(bp * NH + n)) * QQ + q] = tanhf(fmaf(grs, r0, beta));
        g_t1[((size_t)((bp + 8) * NH + n)) * QQ + q] = tanhf(fmaf(grs, r1, beta));
    }
}

// ---------------- ctx-b: cq2 + vcqdot partials ------------------------------
__global__ __launch_bounds__(256) void k_ctx_b(const float* __restrict__ u_q2) {
    int n = blockIdx.y, at = blockIdx.x;
    int tid = threadIdx.x;
    int ai = tid & 31, msl = tid >> 5;
    int a = at * 32 + ai;

    __shared__ float t1_sh[16 * 256];
    __shared__ float part[8 * 16 * 33];

    for (int i = tid; i < 16 * 256; i += 256) {
        int b = i >> 8, m = i & 255;
        t1_sh[i] = g_t1[((size_t)(b * NH + n)) * QQ + m];
    }
    __syncthreads();

    float acc[16];
#pragma unroll
    for (int b = 0; b < 16; b++) acc[b] = 0.f;
    {
        const float* u2 = u_q2 + (size_t)n * QQ * AA + a;
        int m0 = msl * 32;
        for (int m = m0; m < m0 + 32; m++) {
            float w = u2[(size_t)m * AA];
            const float* tb = t1_sh + m;
#pragma unroll
            for (int b = 0; b < 16; b++)
                acc[b] = fmaf(tb[b * 256], w, acc[b]);
        }
    }
#pragma unroll
    for (int b = 0; b < 16; b++) part[(msl * 16 + b) * 33 + ai] = acc[b];
    __syncthreads();
    {
        int bp = tid >> 5;
        float s0 = 0.f, s1 = 0.f;
#pragma unroll
        for (int s = 0; s < 8; s++) {
            s0 += part[(s * 16 + bp) * 33 + ai];
            s1 += part[(s * 16 + bp + 8) * 33 + ai];
        }
        g_cq2[((size_t)(bp * NH + n)) * AA + a] = s0;
        g_cq2[((size_t)((bp + 8) * NH + n)) * AA + a] = s1;

        // vcqdot partials for this atile
        float vs = g_vcqsum[n * AA + a];
        float p0 = s0 * vs, p1 = s1 * vs;
#pragma unroll
        for (int o = 16; o > 0; o >>= 1) {
            p0 += __shfl_down_sync(0xffffffffu, p0, o);
            p1 += __shfl_down_sync(0xffffffffu, p1, o);
        }
        if (ai == 0) {
            g_vcqdotp[(bp * NH + n) * 6 + at] = p0;
            g_vcqdotp[((bp + 8) * NH + n) * 6 + at] = p1;
        }
    }
}

// ---------------- K3: fused scores + softmax-partial kernel ----------------
#define XS_STRIDE 200
#define HK_STRIDE 264
#define SS_STRIDE 100
#define SM_XS 0
#define SM_HK 51200
#define SM_W1A 118784
#define SM_W1B 144384
#define SM_AUX 169984
#define AXH_HCK  (SM_AUX + 0)
#define AXH_KBV  (SM_AUX + 1024)
#define AXH_GRS  (SM_AUX + 2048)
#define AXH_BETA (SM_AUX + 3072)
#define AXH_VHK  (SM_AUX + 4096)
#define AXH_QB   (SM_AUX + 5120)
#define AXH_CQ2  (SM_AUX + 5888)
#define AXH_RS   (SM_AUX + 6656)
#define AXH_LAM  (SM_AUX + 7680)
#define AXH_SCAL (SM_AUX + 8192)
#define SMEM_SC  (SM_AUX + 8448)

__global__ __launch_bounds__(256) void k_scores_mma(
        const float* __restrict__ ht, const float* __restrict__ kb,
        const float* __restrict__ bg, const float* __restrict__ bbias,
        const float* __restrict__ bm, const float* __restrict__ bv,
        const float* __restrict__ vhk, const float* __restrict__ qb) {
    extern __shared__ char smem[];
    uint32_t sb = smem_u32(smem);
    int tid = threadIdx.x;
    int w = tid >> 5, lane = tid & 31;
    int bn = blockIdx.y;
    int b = bn >> 3, n = bn & 7;
    int t0 = blockIdx.x * 128;

    // kick off W1 chunk 0 async load immediately
    {
        const uint4* wsrc = (const uint4*)(g_w1t + (size_t)n * QQ * DD);
#pragma unroll
        for (int it = 0; it < 6; it++) {
            int idx = it * 256 + tid;
            int row = idx / 24, c8 = idx - row * 24;
            CP_ASYNC16(sb + SM_W1A + (row * XS_STRIDE + c8 * 8) * 2, wsrc + idx);
        }
        CP_COMMIT();
    }

    // aux constant arrays + per-bn scalars
    {
        int i = tid;
        float g = bg[i];
        float grs = g * rsqrtf(bv[i] + 1e-5f);
        ((float*)(smem + AXH_GRS))[i] = grs;
        ((float*)(smem + AXH_BETA))[i] = bbias[i] - grs * bm[i];
        ((float*)(smem + AXH_HCK))[i] = g_hck[(size_t)bn * QQ + i];
        ((float*)(smem + AXH_KBV))[i] = kb[n * QQ + i];
        ((float*)(smem + AXH_VHK))[i] = vhk[n * QQ + i];
        if (i < AA) {
            ((float*)(smem + AXH_QB))[i] = qb[n * AA + i];
            ((float*)(smem + AXH_CQ2))[i] = g_cq2[(size_t)bn * AA + i];
        }
        if (i == 0) {
            float qd = 0.f;
#pragma unroll
            for (int k = 0; k < 8; k++) qd += g_qdotp[n * 8 + k];
            float vq = 0.f;
#pragma unroll
            for (int k = 0; k < 6; k++) vq += g_vcqdotp[bn * 6 + k];
            ((float*)(smem + AXH_SCAL))[0] = 1.f / (1.f + __expf(-(qd + vq)));  // lamq
            float ck = 0.f;
#pragma unroll
            for (int k = 0; k < 8; k++) ck += g_ckdotp[bn * 8 + k];
            ((float*)(smem + AXH_SCAL))[1] = ck;
        }
    }

    // ---- load x tile (fp32 -> bf16), rows padded with zeros past TT ----
    {
        const float* xb = ht + ((size_t)b * TT + t0) * CC + n * DD;
        for (int it = 0; it < 24; it++) {
            int idx = it * 256 + tid;
            int row = idx / 48, c4 = idx - row * 48;
            float4 v = make_float4(0.f, 0.f, 0.f, 0.f);
            if (t0 + row < TT) v = *(const float4*)(xb + (size_t)row * CC + c4 * 4);
            uint2 pk = make_uint2(pack_bf(v.x, v.y), pack_bf(v.z, v.w));
            *(uint2*)(smem + SM_XS + (row * XS_STRIDE + c4 * 4) * 2) = pk;
        }
    }

    uint32_t abase = sb + SM_XS + ((w * 16 + (lane & 15)) * XS_STRIDE + (lane >> 4) * 8) * 2;
    uint32_t boff_w1 = (((lane >> 4) * 8 + (lane & 7)) * XS_STRIDE + ((lane >> 3) & 1) * 8) * 2;

    // ---- GEMM1 over 4 q-chunks of 64, double-buffered W1; lambda in regs --
    float lam0 = 0.f, lam1 = 0.f;
    for (int qc = 0; qc < 4; qc++) {
        if (qc < 3) {
            int buf = ((qc + 1) & 1) ? SM_W1B : SM_W1A;
            const uint4* wsrc = (const uint4*)(g_w1t + ((size_t)n * QQ + (qc + 1) * 64) * DD);
#pragma unroll
            for (int it = 0; it < 6; it++) {
                int idx = it * 256 + tid;
                int row = idx / 24, c8 = idx - row * 24;
                CP_ASYNC16(sb + buf + (row * XS_STRIDE + c8 * 8) * 2, wsrc + idx);
            }
            CP_COMMIT();
            CP_WAIT1();
        } else {
            CP_WAIT0();
        }
        __syncthreads();

        uint32_t bbase = sb + ((qc & 1) ? SM_W1B : SM_W1A) + boff_w1;

        float c[4][2][4];
#pragma unroll
        for (int p = 0; p < 4; p++)
#pragma unroll
            for (int j = 0; j < 2; j++)
#pragma unroll
                for (int e = 0; e < 4; e++) c[p][j][e] = 0.f;

        for (int kk = 0; kk < 12; kk++) {
            uint32_t a[4];
            ldsm_x4(a, abase + kk * 32);
#pragma unroll
            for (int p = 0; p < 4; p++) {
                uint32_t bf[4];
                ldsm_x4(bf, bbase + p * 16 * XS_STRIDE * 2 + kk * 32);
                mma_bf16(c[p][0], a, bf[0], bf[1]);
                mma_bf16(c[p][1], a, bf[2], bf[3]);
            }
        }

        const float* vhk_s = (const float*)(smem + AXH_VHK);
        int r0 = w * 16 + (lane >> 2);
#pragma unroll
        for (int p = 0; p < 4; p++) {
#pragma unroll
            for (int j = 0; j < 2; j++) {
                int col = qc * 64 + p * 16 + j * 8 + 2 * (lane & 3);
                float v0 = vhk_s[col], v1 = vhk_s[col + 1];
                lam0 += c[p][j][0] * v0 + c[p][j][1] * v1;
                lam1 += c[p][j][2] * v0 + c[p][j][3] * v1;
                *(uint32_t*)(smem + SM_HK + (r0 * HK_STRIDE + col) * 2) =
                    pack_bf(c[p][j][0], c[p][j][1]);
                *(uint32_t*)(smem + SM_HK + ((r0 + 8) * HK_STRIDE + col) * 2) =
                    pack_bf(c[p][j][2], c[p][j][3]);
            }
        }
        __syncthreads();
    }

    // prefetch qT chunk 0 (a 0..95) into XS region (L2-hot, per-head const)
    {
        const uint4* hs = (const uint4*)(g_qTb + (size_t)n * AA * QQ);
#pragma unroll
        for (int it = 0; it < 12; it++) {
            int idx = it * 256 + tid;
            int row = idx / 32, c8 = idx - row * 32;
            CP_ASYNC16(sb + SM_XS + (row * HK_STRIDE + c8 * 8) * 2, hs + idx);
        }
        CP_COMMIT();
    }

    // lambda finalize
    lam0 += __shfl_xor_sync(0xffffffffu, lam0, 1);
    lam0 += __shfl_xor_sync(0xffffffffu, lam0, 2);
    lam1 += __shfl_xor_sync(0xffffffffu, lam1, 1);
    lam1 += __shfl_xor_sync(0xffffffffu, lam1, 2);
    {
        float ckd = ((const float*)(smem + AXH_SCAL))[1];
        if ((lane & 3) == 0) {
            float* lam_sh = (float*)(smem + AXH_LAM);
            lam_sh[w * 16 + (lane >> 2)] = 1.f / (1.f + __expf(-(lam0 + ckd)));
            lam_sh[w * 16 + (lane >> 2) + 8] = 1.f / (1.f + __expf(-(lam1 + ckd)));
        }
    }
    __syncthreads();

    // ---- activation in place + k2 rowsums (for rank-1 term) ----
    {
        int row = w * 16 + (lane >> 1);
        int cb = (lane & 1) * 128;
        float lam = ((const float*)(smem + AXH_LAM))[row];
        const float* hck_s = (const float*)(smem + AXH_HCK);
        const float* kbv_s = (const float*)(smem + AXH_KBV);
        const float* grs_s = (const float*)(smem + AXH_GRS);
        const float* bet_s = (const float*)(smem + AXH_BETA);
        uint32_t* hp = (uint32_t*)(smem + SM_HK + (row * HK_STRIDE + cb) * 2);
        float rs_acc = 0.f;
        for (int j = 0; j < 16; j++) {
            uint4 v = *(uint4*)(hp + j * 4);
            uint32_t* vr = (uint32_t*)&v;
#pragma unroll
            for (int e = 0; e < 4; e++) {
                int c0 = cb + j * 8 + 2 * e;
                float h0 = bflo(vr[e]), h1 = bfhi(vr[e]);
                float m0 = fmaf(lam, hck_s[c0] - h0, h0) + kbv_s[c0];
                float m1 = fmaf(lam, hck_s[c0 + 1] - h1, h1) + kbv_s[c0 + 1];
                m0 = fmaxf(m0, 0.f); m1 = fmaxf(m1, 0.f);
                float a0 = tanha(fmaf(grs_s[c0], m0, bet_s[c0]));
                float a1 = tanha(fmaf(grs_s[c0 + 1], m1, bet_s[c0 + 1]));
                rs_acc += a0 + a1;
                vr[e] = pack_bf(a0, a1);
            }
            *(uint4*)(hp + j * 4) = v;
        }
        ((float*)(smem + AXH_RS))[(lane & 1) * 128 + row] = rs_acc;
    }

    // ---- GEMM2 over 2 a-chunks of 96 vs qT; rank-1 fused in epilogue ------
    uint32_t abase2 = sb + SM_HK + ((w * 16 + (lane & 15)) * HK_STRIDE + (lane >> 4) * 8) * 2;
    uint32_t boff_hcq = (((lane >> 4) * 8 + (lane & 7)) * HK_STRIDE + ((lane >> 3) & 1) * 8) * 2;
    int r0 = w * 16 + (lane >> 2);

    for (int ac = 0; ac < 2; ac++) {
        if (ac == 0) {
            const uint4* hs = (const uint4*)(g_qTb + ((size_t)n * AA + 96) * QQ);
#pragma unroll
            for (int it = 0; it < 12; it++) {
                int idx = it * 256 + tid;
                int row = idx / 32, c8 = idx - row * 32;
                CP_ASYNC16(sb + SM_W1A + (row * HK_STRIDE + c8 * 8) * 2, hs + idx);
            }
            CP_COMMIT();
            CP_WAIT1();
        } else {
            CP_WAIT0();
        }
        __syncthreads();

        uint32_t bbase2 = sb + (ac ? SM_W1A : SM_XS) + boff_hcq;

        float c2[6][2][4];
#pragma unroll
        for (int p = 0; p < 6; p++)
#pragma unroll
            for (int j = 0; j < 2; j++)
#pragma unroll
                for (int e = 0; e < 4; e++) c2[p][j][e] = 0.f;

        for (int kk = 0; kk < 16; kk++) {
            uint32_t a[4];
            ldsm_x4(a, abase2 + kk * 32);
#pragma unroll
            for (int p = 0; p < 6; p++) {
                uint32_t bf[4];
                ldsm_x4(bf, bbase2 + p * 16 * HK_STRIDE * 2 + kk * 32);
                mma_bf16(c2[p][0], a, bf[0], bf[1]);
                mma_bf16(c2[p][1], a, bf[2], bf[3]);
            }
        }

        __syncthreads();   // all ldmatrix reads of this chunk's B-region done
        float* sdst = (float*)(smem + (ac ? SM_W1A : SM_XS));
        {
            float lamq = ((const float*)(smem + AXH_SCAL))[0];
            float onem = 1.f - lamq;
            float lqs = lamq * (1.f / 16.f);
            const float* rsp = (const float*)(smem + AXH_RS);
            const float* cq2_s = (const float*)(smem + AXH_CQ2);
            float rsa = (rsp[r0] + rsp[128 + r0]) * lqs;
            float rsb = (rsp[r0 + 8] + rsp[128 + r0 + 8]) * lqs;
#pragma unroll
            for (int p = 0; p < 6; p++) {
#pragma unroll
                for (int j = 0; j < 2; j++) {
                    int col = p * 16 + j * 8 + 2 * (lane & 3);
                    float cqa = cq2_s[ac * 96 + col], cqb = cq2_s[ac * 96 + col + 1];
                    *(float2*)(sdst + r0 * SS_STRIDE + col) = make_float2(
                        fmaf(onem, c2[p][j][0], rsa * cqa),
                        fmaf(onem, c2[p][j][1], rsa * cqb));
                    *(float2*)(sdst + (r0 + 8) * SS_STRIDE + col) = make_float2(
                        fmaf(onem, c2[p][j][2], rsb * cqa),
                        fmaf(onem, c2[p][j][3], rsb * cqb));
                }
            }
        }
    }
    __syncthreads();

    // ---- fused softmax partials: thread == a (192 active) -----------------
    if (tid < AA) {
        int a = tid;
        const float* ssm = (a < 96) ? (const float*)(smem + SM_XS)
                                    : (const float*)(smem + SM_W1A);
        int acol = (a < 96) ? a : (a - 96);
        float qbv = ((const float*)(smem + AXH_QB))[a];
        int tmax = TT - t0; if (tmax > 128) tmax = 128;

        float M = -1e30f;
        for (int t = 0; t < tmax; t++)
            M = fmaxf(M, ssm[t * SS_STRIDE + acol]);
        M += qbv;

        float Z = 0.f, S1 = 0.f, S2 = 0.f;
        const float* vp = ht + ((size_t)b * TT + t0) * CC + n * DD + a;
#pragma unroll 4
        for (int t = 0; t < tmax; t++) {
            float s = ssm[t * SS_STRIDE + acol] + qbv;
            float wv = __expf(s - M);
            float v = vp[(size_t)t * CC];
            Z += wv; S1 += wv * v; S2 += wv * v * v;
        }
        g_pp[((size_t)bn * 16 + blockIdx.x) * AA + a] = make_float4(M, Z, S1, S2);
    }
}

// ---------------- K4: merge 16 tile partials -> output ---------------------
__global__ __launch_bounds__(192) void k_pool_merge(float* __restrict__ out) {
    int bn = blockIdx.x;
    int b = bn >> 3, n = bn & 7;
    int a = threadIdx.x;

    const float4* pp = g_pp + (size_t)bn * 16 * AA + a;
    float M = -1e30f;
#pragma unroll
    for (int s = 0; s < 16; s++) M = fmaxf(M, pp[s * AA].x);
    float Zt = 0.f, S1t = 0.f, S2t = 0.f;
#pragma unroll
    for (int s = 0; s < 16; s++) {
        float4 p = pp[s * AA];
        float c = __expf(p.x - M);
        Zt += p.y * c; S1t += p.z * c; S2t += p.w * c;
    }
    float mu = S1t / Zt;
    float ex2 = S2t / Zt;
    float rh = sqrtf(fmaxf(ex2 - mu * mu, 1e-9f));
    out[(size_t)b * (2 * CC) + n * DD + a] = mu;
    out[(size_t)b * (2 * CC) + CC + n * DD + a] = rh;
}

// ---------------- launcher ------------------------------------------------
extern "C" void kernel_launch(void* const* d_in, const int* in_sizes, int n_in,
                              void* d_out, int out_size) {
    const float* ht       = (const float*)d_in[0];
    const float* k_proj_W = (const float*)d_in[1];
    const float* query    = (const float*)d_in[2];
    const float* uk_W     = (const float*)d_in[3];
    const float* u_q1W    = (const float*)d_in[4];
    const float* u_q2     = (const float*)d_in[5];
    const float* vhq      = (const float*)d_in[6];
    const float* vhk      = (const float*)d_in[7];
    const float* vcq      = (const float*)d_in[8];
    const float* vck      = (const float*)d_in[9];
    const float* k_proj_b = (const float*)d_in[10];
    const float* q_b      = (const float*)d_in[11];
    const float* u_q1b    = (const float*)d_in[12];
    const float* bnc_g    = (const float*)d_in[13];
    const float* bnc_b    = (const float*)d_in[14];
    const float* bnc_m    = (const float*)d_in[15];
    const float* bnc_v    = (const float*)d_in[16];
    const float* bnk_g    = (const float*)d_in[17];
    const float* bnk_b    = (const float*)d_in[18];
    const float* bnk_m    = (const float*)d_in[19];
    const float* bnk_v    = (const float*)d_in[20];
    float* out = (float*)d_out;

    static int smem_set = 0;
    if (!smem_set) {
        cudaFuncSetAttribute(k_scores_mma,
                             cudaFuncAttributeMaxDynamicSharedMemorySize, SMEM_SC);
        smem_set = 1;
    }

    // launch 1: fused front (stats + prepw + prepq + qdot/vcqsum)
    k_front<<<1216, 256>>>(ht, k_proj_W, query, vhq, vcq);

    // launch 2: ctx_a (hck, t1, ckdot partials)
    dim3 ga(8, NH);
    k_ctx_a<<<ga, 256>>>(uk_W, u_q1W, u_q1b, vck, bnc_g, bnc_b, bnc_m, bnc_v);

    // launch 3: ctx_b (cq2, vcqdot partials)
    dim3 gb(6, NH);
    k_ctx_b<<<gb, 256>>>(u_q2);

    // launch 4 (ncu-captured): full-grid fused scores kernel
    dim3 gsc(16, BB * NH);
    k_scores_mma<<<gsc, 256, SMEM_SC>>>(ht, k_proj_b, bnk_g, bnk_b, bnk_m, bnk_v,
                                        vhk, q_b);

    // launch 5: merge
    k_pool_merge<<<BB * NH, AA>>>(out);
}